// round 3
// baseline (speedup 1.0000x reference)
#include <cuda_runtime.h>
#include <math.h>

#define HW     3136
#define CC     128
#define TT     16
#define BB     4
#define BT     64          // B*T
#define SCALE  0.17677669529663687f   // 1/sqrt(32)

// Scratch (device global; no allocations in kernel_launch)
__device__ float g_qkv[(size_t)BT * 384 * HW];   // [bt][comp 0..383][hw]

// ---------------------------------------------------------------------------
// Kernel 1: QKV GEMM over the channel dim:
//   qkv[bt, o, hw] = sum_c w_qkv[o, c] * x[bt, c, hw]
// grid: (HW/64, 384/128, BT), block 256, dynamic smem 98816 B
// ---------------------------------------------------------------------------
__global__ void qkv_gemm_kernel(const float* __restrict__ in,   // [BT, C, HW]
                                const float* __restrict__ Wt,   // [384, C]
                                float* __restrict__ out)        // [BT, 384, HW]
{
    extern __shared__ float smem[];
    float* Wsm = smem;                 // [128][129] padded
    float* Xsm = smem + 128 * 129;     // [128][64]

    const int hw0   = blockIdx.x * 64;
    const int obase = blockIdx.y * 128;
    const int bt    = blockIdx.z;
    const int tid   = threadIdx.x;

    const float* inb = in + (size_t)bt * CC * HW;

    for (int i = tid; i < 128 * 128; i += 256) {
        int o = i >> 7, c = i & 127;
        Wsm[o * 129 + c] = Wt[(size_t)(obase + o) * CC + c];
    }
    for (int i = tid; i < 128 * 64; i += 256) {
        int kc = i >> 6, j = i & 63;
        Xsm[kc * 64 + j] = inb[(size_t)kc * HW + hw0 + j];
    }
    __syncthreads();

    const int tj = tid & 7;        // 8 groups in hw
    const int og = tid >> 3;       // 32 groups in o
    const int o0 = og * 4;
    const int j0 = tj * 8;

    float acc[4][8];
#pragma unroll
    for (int oi = 0; oi < 4; oi++)
#pragma unroll
        for (int jj = 0; jj < 8; jj++) acc[oi][jj] = 0.f;

#pragma unroll 8
    for (int k = 0; k < 128; k++) {
        float4 xa = *(const float4*)&Xsm[k * 64 + j0];
        float4 xb = *(const float4*)&Xsm[k * 64 + j0 + 4];
        float xv[8] = {xa.x, xa.y, xa.z, xa.w, xb.x, xb.y, xb.z, xb.w};
#pragma unroll
        for (int oi = 0; oi < 4; oi++) {
            float w = Wsm[(o0 + oi) * 129 + k];
#pragma unroll
            for (int jj = 0; jj < 8; jj++)
                acc[oi][jj] = fmaf(w, xv[jj], acc[oi][jj]);
        }
    }

#pragma unroll
    for (int oi = 0; oi < 4; oi++) {
        size_t off = ((size_t)bt * 384 + obase + o0 + oi) * HW + hw0 + j0;
        float4 r0 = {acc[oi][0], acc[oi][1], acc[oi][2], acc[oi][3]};
        float4 r1 = {acc[oi][4], acc[oi][5], acc[oi][6], acc[oi][7]};
        *(float4*)&out[off]     = r0;
        *(float4*)&out[off + 4] = r1;
    }
}

// ---------------------------------------------------------------------------
// Kernel 2: fused banded attention + output projection.
// Band: s in [max(0, t-2), t]  (causal AND |t-s| <= 2), <= 3 keys per query.
// Heads: h = c >> 5 (4 heads of d=32).
//
// Per block: one bt, 64 hw columns.
//   Phase A (64 threads): attention weights a[3][4] per hw column.
//   Phase B (256 threads): y[c'=0..127][64] tile in smem (head == thread cg).
//   Phase C (256 threads): out[c][hw] = sum_c' w_proj[c][c'] * y[c'] + b[c].
// grid: (HW/64, BT), block 256, dynamic smem 103936 B
// ---------------------------------------------------------------------------
#define YSTR 68   // padded row stride for Ysm (multiple of 4 for float4)

__global__ void attn_proj_kernel(const float* __restrict__ qkv,   // [BT, 384, HW]
                                 const float* __restrict__ Wp,    // [128, 128]
                                 const float* __restrict__ bias,  // [128]
                                 float* __restrict__ out)         // [BT, 128, HW]
{
    extern __shared__ float smem[];
    float* Wsm = smem;                          // [128][129]
    float* Ysm = smem + 128 * 129;              // [128][YSTR]
    float* Asm = Ysm + 128 * YSTR;              // [3][4][64]

    const int hw0 = blockIdx.x * 64;
    const int bt  = blockIdx.y;
    const int b   = bt >> 4;
    const int t   = bt & 15;
    const int tid = threadIdx.x;

    // Load w_proj tile (coalesced in c')
    for (int i = tid; i < 128 * 128; i += 256) {
        int o = i >> 7, c = i & 127;
        Wsm[o * 129 + c] = Wp[(size_t)o * CC + c];
    }

    // Key/value base pointers for the 3 candidate s (clamped; masked by valid)
    bool valid[3];
    size_t kvbase[3];
#pragma unroll
    for (int i = 0; i < 3; i++) {
        int s = t - 2 + i;
        valid[i] = (s >= 0);
        if (s < 0) s = 0;
        kvbase[i] = (size_t)(b * TT + s) * 384 * HW;
    }

    // ---- Phase A: 64 threads compute attention weights for their hw column
    if (tid < 64) {
        const int hw = hw0 + tid;
        const float* qp = qkv + (size_t)bt * 384 * HW + hw;

        float sc[3][4];
#pragma unroll
        for (int i = 0; i < 3; i++)
#pragma unroll
            for (int h = 0; h < 4; h++) sc[i][h] = 0.f;

        const float* k0 = qkv + kvbase[0] + (size_t)128 * HW + hw;
        const float* k1 = qkv + kvbase[1] + (size_t)128 * HW + hw;
        const float* k2 = qkv + kvbase[2] + (size_t)128 * HW + hw;

#pragma unroll 8
        for (int c = 0; c < 128; c++) {
            float qv = qp[(size_t)c * HW];
            int h = c >> 5;
            sc[0][h] = fmaf(qv, k0[(size_t)c * HW], sc[0][h]);
            sc[1][h] = fmaf(qv, k1[(size_t)c * HW], sc[1][h]);
            sc[2][h] = fmaf(qv, k2[(size_t)c * HW], sc[2][h]);
        }

#pragma unroll
        for (int h = 0; h < 4; h++) {
            float m = -1e30f;
#pragma unroll
            for (int i = 0; i < 3; i++)
                if (valid[i]) m = fmaxf(m, sc[i][h] * SCALE);
            float e[3], sum = 0.f;
#pragma unroll
            for (int i = 0; i < 3; i++) {
                e[i] = valid[i] ? expf(sc[i][h] * SCALE - m) : 0.f;
                sum += e[i];
            }
            float inv = 1.f / sum;
#pragma unroll
            for (int i = 0; i < 3; i++)
                Asm[(i * 4 + h) * 64 + tid] = e[i] * inv;
        }
    }
    __syncthreads();

    // ---- Phase B: build y tile. cg = head handled by this thread.
    {
        const int cg = tid >> 6;        // 0..3  == head (c' >> 5 for this group)
        const int j  = tid & 63;
        const int hw = hw0 + j;

        float a0 = Asm[(0 * 4 + cg) * 64 + j];
        float a1 = Asm[(1 * 4 + cg) * 64 + j];
        float a2 = Asm[(2 * 4 + cg) * 64 + j];

        const float* v0 = qkv + kvbase[0] + (size_t)(256 + cg * 32) * HW + hw;
        const float* v1 = qkv + kvbase[1] + (size_t)(256 + cg * 32) * HW + hw;
        const float* v2 = qkv + kvbase[2] + (size_t)(256 + cg * 32) * HW + hw;

#pragma unroll 8
        for (int r = 0; r < 32; r++) {
            float yv = a0 * v0[(size_t)r * HW];
            yv = fmaf(a1, v1[(size_t)r * HW], yv);
            yv = fmaf(a2, v2[(size_t)r * HW], yv);
            Ysm[(cg * 32 + r) * YSTR + j] = yv;
        }
    }
    __syncthreads();

    // ---- Phase C: proj GEMM from smem, write out + bias
    const int tj = tid & 7;
    const int og = tid >> 3;
    const int o0 = og * 4;
    const int j0 = tj * 8;

    float acc[4][8];
#pragma unroll
    for (int oi = 0; oi < 4; oi++)
#pragma unroll
        for (int jj = 0; jj < 8; jj++) acc[oi][jj] = 0.f;

#pragma unroll 8
    for (int k = 0; k < 128; k++) {
        float4 xa = *(const float4*)&Ysm[k * YSTR + j0];
        float4 xb = *(const float4*)&Ysm[k * YSTR + j0 + 4];
        float xv[8] = {xa.x, xa.y, xa.z, xa.w, xb.x, xb.y, xb.z, xb.w};
#pragma unroll
        for (int oi = 0; oi < 4; oi++) {
            float w = Wsm[(o0 + oi) * 129 + k];
#pragma unroll
            for (int jj = 0; jj < 8; jj++)
                acc[oi][jj] = fmaf(w, xv[jj], acc[oi][jj]);
        }
    }

#pragma unroll
    for (int oi = 0; oi < 4; oi++) {
        float bv = bias[o0 + oi];
        size_t off = ((size_t)bt * CC + o0 + oi) * HW + hw0 + j0;
        float4 r0 = {acc[oi][0] + bv, acc[oi][1] + bv, acc[oi][2] + bv, acc[oi][3] + bv};
        float4 r1 = {acc[oi][4] + bv, acc[oi][5] + bv, acc[oi][6] + bv, acc[oi][7] + bv};
        *(float4*)&out[off]     = r0;
        *(float4*)&out[off + 4] = r1;
    }
}

// ---------------------------------------------------------------------------
// kernel_launch
// ---------------------------------------------------------------------------
extern "C" void kernel_launch(void* const* d_in, const int* in_sizes, int n_in,
                              void* d_out, int out_size)
{
    const float* x      = (const float*)d_in[0];  // [B,T,C,H,W]
    const float* w_qkv  = (const float*)d_in[1];  // [384,128]
    const float* w_proj = (const float*)d_in[2];  // [128,128]
    const float* b_proj = (const float*)d_in[3];  // [128]
    float* out = (float*)d_out;                   // [B,T,C,H,W]

    float* qkv_s = nullptr;
    cudaGetSymbolAddress((void**)&qkv_s, g_qkv);

    const int smem1 = (128 * 129 + 128 * 64) * (int)sizeof(float);            // 98816
    const int smem2 = (128 * 129 + 128 * YSTR + 3 * 4 * 64) * (int)sizeof(float); // 103936
    cudaFuncSetAttribute(qkv_gemm_kernel,
                         cudaFuncAttributeMaxDynamicSharedMemorySize, smem1);
    cudaFuncSetAttribute(attn_proj_kernel,
                         cudaFuncAttributeMaxDynamicSharedMemorySize, smem2);

    // 1) QKV GEMM: [BT,384,HW] = w_qkv @ x
    {
        dim3 grid(HW / 64, 384 / 128, BT);
        qkv_gemm_kernel<<<grid, 256, smem1>>>(x, w_qkv, qkv_s);
    }
    // 2) Fused banded attention + projection -> out (already [B,T,C,H,W])
    {
        dim3 grid(HW / 64, BT);
        attn_proj_kernel<<<grid, 256, smem2>>>(qkv_s, w_proj, b_proj, out);
    }
}

// round 8
// speedup vs baseline: 1.3013x; 1.3013x over previous
#include <cuda_runtime.h>
#include <cuda_bf16.h>
#include <cstdint>
#include <math.h>

#define HW     3136
#define CC     128
#define TT     16
#define BB     4
#define BT     64          // B*T
#define SCALE  0.17677669529663687f   // 1/sqrt(32)

// ---------------------------------------------------------------------------
// Scratch (device globals; no allocations in kernel_launch)
// ---------------------------------------------------------------------------
__device__ float g_qkv[(size_t)BT * 384 * HW];      // [bt][comp 0..383][hw]
// K-extended split-bf16 weights: row o (384), cols k (384):
//   k in [0,128)   = bf16_hi(W[o][k])
//   k in [128,256) = bf16_hi(W[o][k-128])      (pairs with X_lo)
//   k in [256,384) = bf16_lo(W[o][k-256])      (pairs with X_hi)
__device__ __nv_bfloat16 g_wk[384 * 384];

__device__ __forceinline__ uint32_t smem_to_u32(const void* smem_ptr) {
    uint32_t addr;
    asm("{ .reg .u64 tmp; cvta.to.shared.u64 tmp, %1; cvt.u32.u64 %0, tmp; }"
        : "=r"(addr) : "l"(smem_ptr));
    return addr;
}

// ldmatrix x4: 4 8x8 b16 tiles; lanes [8i,8i+8) give row addresses of tile i.
#define LDSM4(r0, r1, r2, r3, addr) \
    asm volatile("ldmatrix.sync.aligned.m8n8.x4.shared.b16 {%0,%1,%2,%3}, [%4];" \
        : "=r"(r0), "=r"(r1), "=r"(r2), "=r"(r3) : "r"(addr))

// D(16x8,f32) += A(16x16,bf16,row) * B(16x8,bf16,col)
#define MMA_BF16(d, a0, a1, a2, a3, b0, b1) \
    asm volatile("mma.sync.aligned.m16n8k16.row.col.f32.bf16.bf16.f32 " \
        "{%0,%1,%2,%3}, {%4,%5,%6,%7}, {%8,%9}, {%0,%1,%2,%3};" \
        : "+f"((d)[0]), "+f"((d)[1]), "+f"((d)[2]), "+f"((d)[3]) \
        : "r"(a0), "r"(a1), "r"(a2), "r"(a3), "r"(b0), "r"(b1))

// ---------------------------------------------------------------------------
// Prep: build K-extended split-bf16 weights in gmem (linear [o][384]).
// ---------------------------------------------------------------------------
__global__ void prep_w_kernel(const float* __restrict__ W) {
    for (int i = threadIdx.x; i < 384 * 128; i += blockDim.x) {
        int o = i >> 7;
        int c = i & 127;
        float v = W[(size_t)o * CC + c];
        __nv_bfloat16 hi = __float2bfloat16(v);
        __nv_bfloat16 lo = __float2bfloat16(v - __bfloat162float(hi));
        g_wk[o * 384 + c]       = hi;
        g_wk[o * 384 + 128 + c] = hi;
        g_wk[o * 384 + 256 + c] = lo;
    }
}

// ---------------------------------------------------------------------------
// Kernel 1: QKV GEMM via mma.sync bf16 (split-bf16, K-ext 384).
//   qkv[bt, o, hw] = sum_c W[o,c] * X[bt,c,hw]
// grid (49, 64), block 256 (8 warps), dyn smem 83968 B, 2 CTAs/SM.
// SMEM: Bsm [64 hw][392 k] bf16 @0 (50176B)
//       Asm [32 o ][392 k] bf16 @50176 (25088B)
//       Dsm [32 o ][68 hw] f32  @75264 (8704B)
// ---------------------------------------------------------------------------
#define RSE   392          // smem row stride, elems (bf16)
#define RSB   784          // smem row stride, bytes
#define AOFF  50176
#define DOFF  75264
#define SMEM_QKV 83968

__global__ void __launch_bounds__(256, 2)
qkv_mma_kernel(const float* __restrict__ x, float* __restrict__ out)
{
    extern __shared__ char smem[];
    const uint32_t sb = smem_to_u32(smem);
    __nv_bfloat16* Bsm = reinterpret_cast<__nv_bfloat16*>(smem);
    float*         Dsm = reinterpret_cast<float*>(smem + DOFF);

    const int tid  = threadIdx.x;
    const int wid  = tid >> 5;
    const int lane = tid & 31;
    const int hw0  = blockIdx.x * 64;
    const int bt   = blockIdx.y;

    // ---- Build B: X[c][hw0+j] -> Bsm[j][c]=hi, [j][128+c]=lo, [j][256+c]=hi
    {
        const float* xb = x + (size_t)bt * CC * HW;
        for (int i = tid; i < 64 * 128; i += 256) {
            int c = i >> 6;
            int j = i & 63;
            float v = xb[(size_t)c * HW + hw0 + j];
            __nv_bfloat16 hi = __float2bfloat16(v);
            __nv_bfloat16 lo = __float2bfloat16(v - __bfloat162float(hi));
            Bsm[j * RSE + c]       = hi;
            Bsm[j * RSE + 128 + c] = lo;
            Bsm[j * RSE + 256 + c] = hi;
        }
    }

    // Warp tiling: 2 (m) x 4 (n) warps; warp tile 16(o) x 16(hw).
    const int m0l = (wid >> 2) * 16;
    const int n0  = (wid & 3) * 16;

    // ldmatrix per-lane base addresses (k advances by 32B per k16-step).
    // A x4: tiles {(r0-7,k0),(r8-15,k0),(r0-7,k8),(r8-15,k8)}
    const int rowA = m0l + (lane & 7) + ((lane >> 3) & 1) * 8;
    const int kA   = (lane >> 4) * 8;
    const uint32_t aBase = sb + AOFF + rowA * RSB + kA * 2;
    // B x4: tiles {(n0-7,k0),(n0-7,k8),(n8-15,k0),(n8-15,k8)}
    const int rowB = n0 + (lane & 7) + (lane >> 4) * 8;
    const int kB   = ((lane >> 3) & 1) * 8;
    const uint32_t bBase = sb + rowB * RSB + kB * 2;

    const int gid = lane >> 2;
    const int tg  = lane & 3;

    for (int mt = 0; mt < 12; mt++) {
        const int o0 = mt * 32;
        // ---- Copy A chunk (32 rows x 384 k) from g_wk, uint4 moves
        {
            uint4*       dst = reinterpret_cast<uint4*>(smem + AOFF);
            const uint4* src = reinterpret_cast<const uint4*>(g_wk);
            for (int i = tid; i < 32 * 48; i += 256) {
                int r = i / 48;
                int q = i - r * 48;
                dst[r * 49 + q] = src[(size_t)(o0 + r) * 48 + q];
            }
        }
        __syncthreads();

        // ---- Compute: 24 k16-steps over K=384
        float d0[4] = {0.f, 0.f, 0.f, 0.f};
        float d1[4] = {0.f, 0.f, 0.f, 0.f};
#pragma unroll
        for (int ks = 0; ks < 24; ks++) {
            uint32_t a0, a1, a2, a3, b0, b1, b2, b3;
            LDSM4(a0, a1, a2, a3, aBase + ks * 32);
            LDSM4(b0, b1, b2, b3, bBase + ks * 32);
            MMA_BF16(d0, a0, a1, a2, a3, b0, b1);
            MMA_BF16(d1, a0, a1, a2, a3, b2, b3);
        }

        // ---- D frags -> Dsm
        {
            int r = m0l + gid;
            Dsm[r * 68 + n0 + 2 * tg]           = d0[0];
            Dsm[r * 68 + n0 + 2 * tg + 1]       = d0[1];
            Dsm[(r + 8) * 68 + n0 + 2 * tg]     = d0[2];
            Dsm[(r + 8) * 68 + n0 + 2 * tg + 1] = d0[3];
            Dsm[r * 68 + n0 + 8 + 2 * tg]           = d1[0];
            Dsm[r * 68 + n0 + 8 + 2 * tg + 1]       = d1[1];
            Dsm[(r + 8) * 68 + n0 + 8 + 2 * tg]     = d1[2];
            Dsm[(r + 8) * 68 + n0 + 8 + 2 * tg + 1] = d1[3];
        }
        __syncthreads();

        // ---- Coalesced store: 32 rows x 64 hw
        {
            int o  = tid >> 3;
            int jb = (tid & 7) * 8;
            const float* srow = Dsm + o * 68 + jb;
            float* dst = out + ((size_t)bt * 384 + o0 + o) * HW + hw0 + jb;
            float4 v0;
            v0.x = srow[0]; v0.y = srow[1]; v0.z = srow[2]; v0.w = srow[3];
            float4 v1;
            v1.x = srow[4]; v1.y = srow[5]; v1.z = srow[6]; v1.w = srow[7];
            *reinterpret_cast<float4*>(dst)     = v0;
            *reinterpret_cast<float4*>(dst + 4) = v1;
        }
        __syncthreads();   // Asm/Dsm reused next chunk
    }
}

// ---------------------------------------------------------------------------
// Kernel 2: fused banded attention + output projection.
// Occupancy fix: W chunked to 64 rows (2 passes) -> 71KB smem, 3 CTAs/SM.
// grid (49, 64), block 256.
// ---------------------------------------------------------------------------
#define YSTR 68

__global__ void __launch_bounds__(256, 3)
attn_proj_kernel(const float* __restrict__ qkv,
                 const float* __restrict__ Wp,
                 const float* __restrict__ bias,
                 float* __restrict__ out)
{
    extern __shared__ float smemf[];
    float* Wsm = smemf;                  // [64][129]   33024 B
    float* Ysm = smemf + 64 * 129;       // [128][YSTR] 34816 B
    float* Asm = Ysm + 128 * YSTR;       // [3][4][64]   3072 B

    const int hw0 = blockIdx.x * 64;
    const int bt  = blockIdx.y;
    const int b   = bt >> 4;
    const int t   = bt & 15;
    const int tid = threadIdx.x;

    bool valid[3];
    size_t kvbase[3];
#pragma unroll
    for (int i = 0; i < 3; i++) {
        int s = t - 2 + i;
        valid[i] = (s >= 0);
        if (s < 0) s = 0;
        kvbase[i] = (size_t)(b * TT + s) * 384 * HW;
    }

    // ---- Phase A: attention weights (64 threads, one per hw column)
    if (tid < 64) {
        const int hw = hw0 + tid;
        const float* qp = qkv + (size_t)bt * 384 * HW + hw;
        float sc[3][4];
#pragma unroll
        for (int i = 0; i < 3; i++) {
#pragma unroll
            for (int h = 0; h < 4; h++) sc[i][h] = 0.f;
        }
        const float* k0 = qkv + kvbase[0] + (size_t)128 * HW + hw;
        const float* k1 = qkv + kvbase[1] + (size_t)128 * HW + hw;
        const float* k2 = qkv + kvbase[2] + (size_t)128 * HW + hw;
#pragma unroll 8
        for (int c = 0; c < 128; c++) {
            float qv = qp[(size_t)c * HW];
            int h = c >> 5;
            sc[0][h] = fmaf(qv, k0[(size_t)c * HW], sc[0][h]);
            sc[1][h] = fmaf(qv, k1[(size_t)c * HW], sc[1][h]);
            sc[2][h] = fmaf(qv, k2[(size_t)c * HW], sc[2][h]);
        }
#pragma unroll
        for (int h = 0; h < 4; h++) {
            float m = -1e30f;
#pragma unroll
            for (int i = 0; i < 3; i++) {
                if (valid[i]) m = fmaxf(m, sc[i][h] * SCALE);
            }
            float e[3];
            float sum = 0.f;
#pragma unroll
            for (int i = 0; i < 3; i++) {
                e[i] = valid[i] ? expf(sc[i][h] * SCALE - m) : 0.f;
                sum += e[i];
            }
            float inv = 1.f / sum;
#pragma unroll
            for (int i = 0; i < 3; i++) {
                Asm[(i * 4 + h) * 64 + tid] = e[i] * inv;
            }
        }
    }
    __syncthreads();

    // ---- Phase B: build Y tile [128 c'][64 hw]
    {
        const int cg = tid >> 6;        // head
        const int j  = tid & 63;
        const int hw = hw0 + j;
        float a0 = Asm[(0 * 4 + cg) * 64 + j];
        float a1 = Asm[(1 * 4 + cg) * 64 + j];
        float a2 = Asm[(2 * 4 + cg) * 64 + j];
        const float* v0 = qkv + kvbase[0] + (size_t)(256 + cg * 32) * HW + hw;
        const float* v1 = qkv + kvbase[1] + (size_t)(256 + cg * 32) * HW + hw;
        const float* v2 = qkv + kvbase[2] + (size_t)(256 + cg * 32) * HW + hw;
#pragma unroll 8
        for (int r = 0; r < 32; r++) {
            float yv = a0 * v0[(size_t)r * HW];
            yv = fmaf(a1, v1[(size_t)r * HW], yv);
            yv = fmaf(a2, v2[(size_t)r * HW], yv);
            Ysm[(cg * 32 + r) * YSTR + j] = yv;
        }
    }
    __syncthreads();

    // ---- Phase C: projection in two 64-row W chunks
    const int og  = tid >> 3;           // 0..31
    const int o0l = og * 2;
    const int pj0 = (tid & 7) * 8;

    for (int half = 0; half < 2; half++) {
        // load W chunk rows [half*64, half*64+64)
        for (int i = tid; i < 64 * 128; i += 256) {
            int o = i >> 7;
            int c = i & 127;
            Wsm[o * 129 + c] = Wp[(size_t)(half * 64 + o) * CC + c];
        }
        __syncthreads();

        float acc[2][8];
#pragma unroll
        for (int oi = 0; oi < 2; oi++) {
#pragma unroll
            for (int jj = 0; jj < 8; jj++) acc[oi][jj] = 0.f;
        }
#pragma unroll 8
        for (int k = 0; k < 128; k++) {
            float4 xa = *reinterpret_cast<const float4*>(&Ysm[k * YSTR + pj0]);
            float4 xb = *reinterpret_cast<const float4*>(&Ysm[k * YSTR + pj0 + 4]);
            float xv[8] = {xa.x, xa.y, xa.z, xa.w, xb.x, xb.y, xb.z, xb.w};
#pragma unroll
            for (int oi = 0; oi < 2; oi++) {
                float w = Wsm[(o0l + oi) * 129 + k];
#pragma unroll
                for (int jj = 0; jj < 8; jj++) {
                    acc[oi][jj] = fmaf(w, xv[jj], acc[oi][jj]);
                }
            }
        }

#pragma unroll
        for (int oi = 0; oi < 2; oi++) {
            int o_g = half * 64 + o0l + oi;
            float bv = bias[o_g];
            size_t off = ((size_t)bt * CC + o_g) * HW + hw0 + pj0;
            float4 r0;
            r0.x = acc[oi][0] + bv; r0.y = acc[oi][1] + bv;
            r0.z = acc[oi][2] + bv; r0.w = acc[oi][3] + bv;
            float4 r1;
            r1.x = acc[oi][4] + bv; r1.y = acc[oi][5] + bv;
            r1.z = acc[oi][6] + bv; r1.w = acc[oi][7] + bv;
            *reinterpret_cast<float4*>(&out[off])     = r0;
            *reinterpret_cast<float4*>(&out[off + 4]) = r1;
        }
        __syncthreads();   // before W chunk reload
    }
}

// ---------------------------------------------------------------------------
// kernel_launch
// ---------------------------------------------------------------------------
extern "C" void kernel_launch(void* const* d_in, const int* in_sizes, int n_in,
                              void* d_out, int out_size)
{
    const float* x      = (const float*)d_in[0];
    const float* w_qkv  = (const float*)d_in[1];
    const float* w_proj = (const float*)d_in[2];
    const float* b_proj = (const float*)d_in[3];
    float* out = (float*)d_out;

    float* qkv_s = nullptr;
    cudaGetSymbolAddress((void**)&qkv_s, g_qkv);

    cudaFuncSetAttribute(qkv_mma_kernel,
                         cudaFuncAttributeMaxDynamicSharedMemorySize, SMEM_QKV);
    const int smem2 = (64 * 129 + 128 * YSTR + 3 * 4 * 64) * (int)sizeof(float); // 70912
    cudaFuncSetAttribute(attn_proj_kernel,
                         cudaFuncAttributeMaxDynamicSharedMemorySize, smem2);

    // 0) K-extended split-bf16 weights
    prep_w_kernel<<<1, 256>>>(w_qkv);
    // 1) QKV GEMM on tensor cores (mma.sync bf16)
    {
        dim3 grid(HW / 64, BT);
        qkv_mma_kernel<<<grid, 256, SMEM_QKV>>>(x, qkv_s);
    }
    // 2) Fused banded attention + projection
    {
        dim3 grid(HW / 64, BT);
        attn_proj_kernel<<<grid, 256, smem2>>>(qkv_s, w_proj, b_proj, out);
    }
}

// round 9
// speedup vs baseline: 1.7010x; 1.3072x over previous
#include <cuda_runtime.h>
#include <cuda_bf16.h>
#include <cstdint>
#include <math.h>

#define HW     3136
#define CC     128
#define TT     16
#define BB     4
#define BT     64          // B*T
#define SCALE  0.17677669529663687f   // 1/sqrt(32)

// ---------------------------------------------------------------------------
// Scratch (device globals; no allocations in kernel_launch)
// ---------------------------------------------------------------------------
__device__ float g_qkv[(size_t)BT * 384 * HW];      // [bt][comp 0..383][hw]
// K-extended split-bf16 weights, row-major [o][384]:
//   k in [0,128)   = bf16_hi(W[o][k])        (pairs with X_hi)
//   k in [128,256) = bf16_hi(W[o][k-128])    (pairs with X_lo)
//   k in [256,384) = bf16_lo(W[o][k-256])    (pairs with X_hi)
__device__ __nv_bfloat16 g_wk [384 * 384];          // w_qkv
__device__ __nv_bfloat16 g_wpk[128 * 384];          // w_proj

__device__ __forceinline__ uint32_t smem_to_u32(const void* smem_ptr) {
    uint32_t addr;
    asm("{ .reg .u64 tmp; cvta.to.shared.u64 tmp, %1; cvt.u32.u64 %0, tmp; }"
        : "=r"(addr) : "l"(smem_ptr));
    return addr;
}

// ldmatrix x4: 4 8x8 b16 tiles; lanes [8i,8i+8) give row addresses of tile i.
#define LDSM4(r0, r1, r2, r3, addr) \
    asm volatile("ldmatrix.sync.aligned.m8n8.x4.shared.b16 {%0,%1,%2,%3}, [%4];" \
        : "=r"(r0), "=r"(r1), "=r"(r2), "=r"(r3) : "r"(addr))

// D(16x8,f32) += A(16x16,bf16,row) * B(16x8,bf16,col)
#define MMA_BF16(d, a0, a1, a2, a3, b0, b1) \
    asm volatile("mma.sync.aligned.m16n8k16.row.col.f32.bf16.bf16.f32 " \
        "{%0,%1,%2,%3}, {%4,%5,%6,%7}, {%8,%9}, {%0,%1,%2,%3};" \
        : "+f"((d)[0]), "+f"((d)[1]), "+f"((d)[2]), "+f"((d)[3]) \
        : "r"(a0), "r"(a1), "r"(a2), "r"(a3), "r"(b0), "r"(b1))

// ---------------------------------------------------------------------------
// Prep: K-extended split-bf16 weights for BOTH gemms. grid 128 x 256.
// ---------------------------------------------------------------------------
__global__ void prep_w_kernel(const float* __restrict__ Wqkv,
                              const float* __restrict__ Wproj)
{
    const int gtid = blockIdx.x * blockDim.x + threadIdx.x;
    const int nthr = gridDim.x * blockDim.x;
    // w_qkv: 384 x 128
    for (int i = gtid; i < 384 * 128; i += nthr) {
        int o = i >> 7;
        int c = i & 127;
        float v = Wqkv[(size_t)o * CC + c];
        __nv_bfloat16 hi = __float2bfloat16(v);
        __nv_bfloat16 lo = __float2bfloat16(v - __bfloat162float(hi));
        g_wk[o * 384 + c]       = hi;
        g_wk[o * 384 + 128 + c] = hi;
        g_wk[o * 384 + 256 + c] = lo;
    }
    // w_proj: 128 x 128
    for (int i = gtid; i < 128 * 128; i += nthr) {
        int o = i >> 7;
        int c = i & 127;
        float v = Wproj[(size_t)o * CC + c];
        __nv_bfloat16 hi = __float2bfloat16(v);
        __nv_bfloat16 lo = __float2bfloat16(v - __bfloat162float(hi));
        g_wpk[o * 384 + c]       = hi;
        g_wpk[o * 384 + 128 + c] = hi;
        g_wpk[o * 384 + 256 + c] = lo;
    }
}

// ---------------------------------------------------------------------------
// Kernel 1: QKV GEMM via mma.sync bf16 (split-bf16, K-ext 384).
// grid (49, 64), block 256 (8 warps), dyn smem 75264 B, up to 3 CTAs/SM.
// SMEM: Bsm [64 hw][392 k] bf16 @0 (50176B); Asm [32 o][392 k] bf16 @50176.
// Direct fragment->gmem stores (each 4-lane group writes one 32B sector).
// ---------------------------------------------------------------------------
#define RSE   392          // smem row stride, elems (bf16)
#define RSB   784          // smem row stride, bytes
#define AOFF  50176
#define SMEM_QKV 75264

__global__ void __launch_bounds__(256, 3)
qkv_mma_kernel(const float* __restrict__ x, float* __restrict__ out)
{
    extern __shared__ char smem[];
    const uint32_t sb = smem_to_u32(smem);
    __nv_bfloat16* Bsm = reinterpret_cast<__nv_bfloat16*>(smem);

    const int tid  = threadIdx.x;
    const int wid  = tid >> 5;
    const int lane = tid & 31;
    const int hw0  = blockIdx.x * 64;
    const int bt   = blockIdx.y;

    // ---- Build B: X[c][hw0+j] -> Bsm[j][c]=hi, [j][128+c]=lo, [j][256+c]=hi
    {
        const float* xb = x + (size_t)bt * CC * HW;
        for (int i = tid; i < 64 * 128; i += 256) {
            int c = i >> 6;
            int j = i & 63;
            float v = xb[(size_t)c * HW + hw0 + j];
            __nv_bfloat16 hi = __float2bfloat16(v);
            __nv_bfloat16 lo = __float2bfloat16(v - __bfloat162float(hi));
            Bsm[j * RSE + c]       = hi;
            Bsm[j * RSE + 128 + c] = lo;
            Bsm[j * RSE + 256 + c] = hi;
        }
    }

    // Warp tiling: 2 (m) x 4 (n); warp tile 16(o) x 16(hw).
    const int m0l = (wid >> 2) * 16;
    const int n0  = (wid & 3) * 16;

    const int rowA = m0l + (lane & 7) + ((lane >> 3) & 1) * 8;
    const int kA   = (lane >> 4) * 8;
    const uint32_t aBase = sb + AOFF + rowA * RSB + kA * 2;
    const int rowB = n0 + (lane & 7) + (lane >> 4) * 8;
    const int kB   = ((lane >> 3) & 1) * 8;
    const uint32_t bBase = sb + rowB * RSB + kB * 2;

    const int gid = lane >> 2;
    const int tg  = lane & 3;

    for (int mt = 0; mt < 12; mt++) {
        const int o0 = mt * 32;
        // ---- Copy A chunk (32 rows x 384 k) from g_wk, uint4 moves
        {
            uint4*       dst = reinterpret_cast<uint4*>(smem + AOFF);
            const uint4* src = reinterpret_cast<const uint4*>(g_wk);
            for (int i = tid; i < 32 * 48; i += 256) {
                int r = i / 48;
                int q = i - r * 48;
                dst[r * 49 + q] = src[(size_t)(o0 + r) * 48 + q];
            }
        }
        __syncthreads();

        // ---- Compute: 24 k16-steps over K=384
        float d0[4] = {0.f, 0.f, 0.f, 0.f};
        float d1[4] = {0.f, 0.f, 0.f, 0.f};
#pragma unroll
        for (int ks = 0; ks < 24; ks++) {
            uint32_t a0, a1, a2, a3, b0, b1, b2, b3;
            LDSM4(a0, a1, a2, a3, aBase + ks * 32);
            LDSM4(b0, b1, b2, b3, bBase + ks * 32);
            MMA_BF16(d0, a0, a1, a2, a3, b0, b1);
            MMA_BF16(d1, a0, a1, a2, a3, b2, b3);
        }

        // ---- Direct stores: lane group (gid) covers a 32B sector per row
        {
            int r0g = o0 + m0l + gid;           // global o row
            size_t base = (size_t)bt * 384 * HW + hw0;
            float2 v;
            v.x = d0[0]; v.y = d0[1];
            *reinterpret_cast<float2*>(out + base + (size_t)r0g * HW + n0 + 2 * tg) = v;
            v.x = d0[2]; v.y = d0[3];
            *reinterpret_cast<float2*>(out + base + (size_t)(r0g + 8) * HW + n0 + 2 * tg) = v;
            v.x = d1[0]; v.y = d1[1];
            *reinterpret_cast<float2*>(out + base + (size_t)r0g * HW + n0 + 8 + 2 * tg) = v;
            v.x = d1[2]; v.y = d1[3];
            *reinterpret_cast<float2*>(out + base + (size_t)(r0g + 8) * HW + n0 + 8 + 2 * tg) = v;
        }
        __syncthreads();   // Asm reused next chunk
    }
}

// ---------------------------------------------------------------------------
// Kernel 2: fused banded attention + projection, projection on mma.sync.
// grid (49, 64), block 256 (8 warps), dyn smem 103424 B, 2 CTAs/SM.
// SMEM: Wsm bf16 [64 o][392 k] @0; Ybf bf16 [64 hw][392 k] @50176;
//       Attw f32 [12][64] @100352.
// ---------------------------------------------------------------------------
#define YB_OFF 50176
#define AW_OFF 100352
#define SMEM_AP 103424

__global__ void __launch_bounds__(256, 2)
attn_proj_kernel(const float* __restrict__ qkv,
                 const float* __restrict__ bias,
                 float* __restrict__ out)
{
    extern __shared__ char smem[];
    const uint32_t sb = smem_to_u32(smem);
    __nv_bfloat16* Ybf  = reinterpret_cast<__nv_bfloat16*>(smem + YB_OFF);
    float*         Attw = reinterpret_cast<float*>(smem + AW_OFF);

    const int hw0 = blockIdx.x * 64;
    const int bt  = blockIdx.y;
    const int b   = bt >> 4;
    const int t   = bt & 15;
    const int tid = threadIdx.x;
    const int wid  = tid >> 5;
    const int lane = tid & 31;

    bool valid[3];
    size_t kvbase[3];
#pragma unroll
    for (int i = 0; i < 3; i++) {
        int s = t - 2 + i;
        valid[i] = (s >= 0);
        if (s < 0) s = 0;
        kvbase[i] = (size_t)(b * TT + s) * 384 * HW;
    }

    // ---- Phase A: attention weights (64 threads, one per hw column)
    if (tid < 64) {
        const int hw = hw0 + tid;
        const float* qp = qkv + (size_t)bt * 384 * HW + hw;
        float sc[3][4];
#pragma unroll
        for (int i = 0; i < 3; i++) {
#pragma unroll
            for (int h = 0; h < 4; h++) sc[i][h] = 0.f;
        }
        const float* k0 = qkv + kvbase[0] + (size_t)128 * HW + hw;
        const float* k1 = qkv + kvbase[1] + (size_t)128 * HW + hw;
        const float* k2 = qkv + kvbase[2] + (size_t)128 * HW + hw;
#pragma unroll 8
        for (int c = 0; c < 128; c++) {
            float qv = qp[(size_t)c * HW];
            int h = c >> 5;
            sc[0][h] = fmaf(qv, k0[(size_t)c * HW], sc[0][h]);
            sc[1][h] = fmaf(qv, k1[(size_t)c * HW], sc[1][h]);
            sc[2][h] = fmaf(qv, k2[(size_t)c * HW], sc[2][h]);
        }
#pragma unroll
        for (int h = 0; h < 4; h++) {
            float m = -1e30f;
#pragma unroll
            for (int i = 0; i < 3; i++) {
                if (valid[i]) m = fmaxf(m, sc[i][h] * SCALE);
            }
            float e[3];
            float sum = 0.f;
#pragma unroll
            for (int i = 0; i < 3; i++) {
                e[i] = valid[i] ? expf(sc[i][h] * SCALE - m) : 0.f;
                sum += e[i];
            }
            float inv = 1.f / sum;
#pragma unroll
            for (int i = 0; i < 3; i++) {
                Attw[(i * 4 + h) * 64 + tid] = e[i] * inv;
            }
        }
    }
    __syncthreads();

    // ---- Phase B: build Y tile as split-bf16 K-ext rows [hw j][k]
    {
        const int cg = tid >> 6;        // head = c' >> 5
        const int j  = tid & 63;
        const int hw = hw0 + j;
        float a0 = Attw[(0 * 4 + cg) * 64 + j];
        float a1 = Attw[(1 * 4 + cg) * 64 + j];
        float a2 = Attw[(2 * 4 + cg) * 64 + j];
        const float* v0 = qkv + kvbase[0] + (size_t)(256 + cg * 32) * HW + hw;
        const float* v1 = qkv + kvbase[1] + (size_t)(256 + cg * 32) * HW + hw;
        const float* v2 = qkv + kvbase[2] + (size_t)(256 + cg * 32) * HW + hw;
#pragma unroll 8
        for (int r = 0; r < 32; r++) {
            float yv = a0 * v0[(size_t)r * HW];
            yv = fmaf(a1, v1[(size_t)r * HW], yv);
            yv = fmaf(a2, v2[(size_t)r * HW], yv);
            __nv_bfloat16 hi = __float2bfloat16(yv);
            __nv_bfloat16 lo = __float2bfloat16(yv - __bfloat162float(hi));
            int cp = cg * 32 + r;
            Ybf[j * RSE + cp]       = hi;
            Ybf[j * RSE + 128 + cp] = lo;
            Ybf[j * RSE + 256 + cp] = hi;
        }
    }
    __syncthreads();

    // ---- Phase C: projection via mma.sync, two 64-row W chunks.
    // Warps: 4 (m) x 2 (n); warp tile 16(o) x 32(hw).
    const int m0l = (wid >> 1) * 16;
    const int n0  = (wid & 1) * 32;

    const int rowA = m0l + (lane & 7) + ((lane >> 3) & 1) * 8;
    const int kA   = (lane >> 4) * 8;
    const uint32_t aBase = sb + rowA * RSB + kA * 2;
    const int rowB = n0 + (lane & 7) + (lane >> 4) * 8;
    const int kB   = ((lane >> 3) & 1) * 8;
    const uint32_t bBase  = sb + YB_OFF + rowB * RSB + kB * 2;
    const uint32_t bBase2 = bBase + 16 * RSB;

    const int gid = lane >> 2;
    const int tg  = lane & 3;

    for (int half = 0; half < 2; half++) {
        // load W chunk rows [half*64, half*64+64) from g_wpk
        {
            uint4*       dst = reinterpret_cast<uint4*>(smem);
            const uint4* src = reinterpret_cast<const uint4*>(g_wpk);
            for (int i = tid; i < 64 * 48; i += 256) {
                int r = i / 48;
                int q = i - r * 48;
                dst[r * 49 + q] = src[(size_t)(half * 64 + r) * 48 + q];
            }
        }
        __syncthreads();

        float d0[4] = {0.f, 0.f, 0.f, 0.f};
        float d1[4] = {0.f, 0.f, 0.f, 0.f};
        float d2[4] = {0.f, 0.f, 0.f, 0.f};
        float d3[4] = {0.f, 0.f, 0.f, 0.f};
#pragma unroll
        for (int ks = 0; ks < 24; ks++) {
            uint32_t a0, a1, a2, a3, b0, b1, b2, b3, c0, c1, c2, c3;
            LDSM4(a0, a1, a2, a3, aBase + ks * 32);
            LDSM4(b0, b1, b2, b3, bBase + ks * 32);
            LDSM4(c0, c1, c2, c3, bBase2 + ks * 32);
            MMA_BF16(d0, a0, a1, a2, a3, b0, b1);
            MMA_BF16(d1, a0, a1, a2, a3, b2, b3);
            MMA_BF16(d2, a0, a1, a2, a3, c0, c1);
            MMA_BF16(d3, a0, a1, a2, a3, c2, c3);
        }

        // ---- Direct stores with bias
        {
            int og0 = half * 64 + m0l + gid;
            int og1 = og0 + 8;
            float bv0 = __ldg(bias + og0);
            float bv1 = __ldg(bias + og1);
            size_t base = (size_t)bt * CC * HW + hw0;
            float* r0p = out + base + (size_t)og0 * HW + n0 + 2 * tg;
            float* r1p = out + base + (size_t)og1 * HW + n0 + 2 * tg;
            float2 v;
            v.x = d0[0] + bv0; v.y = d0[1] + bv0;
            *reinterpret_cast<float2*>(r0p) = v;
            v.x = d0[2] + bv1; v.y = d0[3] + bv1;
            *reinterpret_cast<float2*>(r1p) = v;
            v.x = d1[0] + bv0; v.y = d1[1] + bv0;
            *reinterpret_cast<float2*>(r0p + 8) = v;
            v.x = d1[2] + bv1; v.y = d1[3] + bv1;
            *reinterpret_cast<float2*>(r1p + 8) = v;
            v.x = d2[0] + bv0; v.y = d2[1] + bv0;
            *reinterpret_cast<float2*>(r0p + 16) = v;
            v.x = d2[2] + bv1; v.y = d2[3] + bv1;
            *reinterpret_cast<float2*>(r1p + 16) = v;
            v.x = d3[0] + bv0; v.y = d3[1] + bv0;
            *reinterpret_cast<float2*>(r0p + 24) = v;
            v.x = d3[2] + bv1; v.y = d3[3] + bv1;
            *reinterpret_cast<float2*>(r1p + 24) = v;
        }
        __syncthreads();   // before W chunk reload
    }
}

// ---------------------------------------------------------------------------
// kernel_launch
// ---------------------------------------------------------------------------
extern "C" void kernel_launch(void* const* d_in, const int* in_sizes, int n_in,
                              void* d_out, int out_size)
{
    const float* x      = (const float*)d_in[0];
    const float* w_qkv  = (const float*)d_in[1];
    const float* w_proj = (const float*)d_in[2];
    const float* b_proj = (const float*)d_in[3];
    float* out = (float*)d_out;

    float* qkv_s = nullptr;
    cudaGetSymbolAddress((void**)&qkv_s, g_qkv);

    cudaFuncSetAttribute(qkv_mma_kernel,
                         cudaFuncAttributeMaxDynamicSharedMemorySize, SMEM_QKV);
    cudaFuncSetAttribute(attn_proj_kernel,
                         cudaFuncAttributeMaxDynamicSharedMemorySize, SMEM_AP);

    // 0) K-extended split-bf16 weights (both gemms), parallel grid
    prep_w_kernel<<<128, 256>>>(w_qkv, w_proj);
    // 1) QKV GEMM on tensor cores
    {
        dim3 grid(HW / 64, BT);
        qkv_mma_kernel<<<grid, 256, SMEM_QKV>>>(x, qkv_s);
    }
    // 2) Fused banded attention + projection (projection on tensor cores)
    {
        dim3 grid(HW / 64, BT);
        attn_proj_kernel<<<grid, 256, SMEM_AP>>>(qkv_s, b_proj, out);
    }
}

// round 11
// speedup vs baseline: 2.4533x; 1.4422x over previous
#include <cuda_runtime.h>
#include <cuda_bf16.h>
#include <cstdint>
#include <math.h>

#define HW     3136
#define CC     128
#define TT     16
#define BB     4
#define BT     64          // B*T
#define SCALE  0.17677669529663687f   // 1/sqrt(32)

// ---------------------------------------------------------------------------
// Scratch (device globals; no allocations in kernel_launch)
// ---------------------------------------------------------------------------
__device__ float g_qkv[(size_t)BT * 384 * HW];      // [bt][comp 0..383][hw]
// K-extended split-bf16 weights, row-major [o][384]:
//   k in [0,128)=hi (pairs X_hi); [128,256)=hi (pairs X_lo); [256,384)=lo (pairs X_hi)
__device__ __nv_bfloat16 g_wk [384 * 384];          // w_qkv
__device__ __nv_bfloat16 g_wpk[128 * 384];          // w_proj

__device__ __forceinline__ uint32_t smem_to_u32(const void* smem_ptr) {
    uint32_t addr;
    asm("{ .reg .u64 tmp; cvta.to.shared.u64 tmp, %1; cvt.u32.u64 %0, tmp; }"
        : "=r"(addr) : "l"(smem_ptr));
    return addr;
}

// ldmatrix x4: 4 8x8 b16 tiles; lanes [8i,8i+8) give row addresses of tile i.
#define LDSM4(r0, r1, r2, r3, addr) \
    asm volatile("ldmatrix.sync.aligned.m8n8.x4.shared.b16 {%0,%1,%2,%3}, [%4];" \
        : "=r"(r0), "=r"(r1), "=r"(r2), "=r"(r3) : "r"(addr))

// D(16x8,f32) += A(16x16,bf16,row) * B(16x8,bf16,col)
#define MMA_BF16(d, a0, a1, a2, a3, b0, b1) \
    asm volatile("mma.sync.aligned.m16n8k16.row.col.f32.bf16.bf16.f32 " \
        "{%0,%1,%2,%3}, {%4,%5,%6,%7}, {%8,%9}, {%0,%1,%2,%3};" \
        : "+f"((d)[0]), "+f"((d)[1]), "+f"((d)[2]), "+f"((d)[3]) \
        : "r"(a0), "r"(a1), "r"(a2), "r"(a3), "r"(b0), "r"(b1))

#define CP_ASYNC16(saddr, gptr) \
    asm volatile("cp.async.cg.shared.global [%0], [%1], 16;" \
        :: "r"(saddr), "l"(gptr))
#define CP_COMMIT() asm volatile("cp.async.commit_group;" ::: "memory")
#define CP_WAIT1()  asm volatile("cp.async.wait_group 1;" ::: "memory")

// Issue async copy of one 32-row x 384-col bf16 chunk (src 768B rows) into a
// smem buffer with 784B row stride. 256 threads, 6 x 16B each.
__device__ __forceinline__ void issue_chunk_copy(uint32_t dstBase,
                                                 const __nv_bfloat16* srcRow0,
                                                 int tid)
{
    const int row = tid >> 3;       // 32 rows
    const int q0  = tid & 7;        // 8 lanes, 16B each, step 128B
    const char* src = reinterpret_cast<const char*>(srcRow0)
                    + (size_t)row * 768 + q0 * 16;
    uint32_t dst = dstBase + row * 784 + q0 * 16;
#pragma unroll
    for (int it = 0; it < 6; it++) {
        CP_ASYNC16(dst + it * 128, src + it * 128);
    }
}

// ---------------------------------------------------------------------------
// Prep: K-extended split-bf16 weights for both gemms. grid 128 x 256.
// ---------------------------------------------------------------------------
__global__ void prep_w_kernel(const float* __restrict__ Wqkv,
                              const float* __restrict__ Wproj)
{
    const int gtid = blockIdx.x * blockDim.x + threadIdx.x;
    const int nthr = gridDim.x * blockDim.x;
    for (int i = gtid; i < 384 * 128; i += nthr) {
        int o = i >> 7;
        int c = i & 127;
        float v = Wqkv[(size_t)o * CC + c];
        __nv_bfloat16 hi = __float2bfloat16(v);
        __nv_bfloat16 lo = __float2bfloat16(v - __bfloat162float(hi));
        g_wk[o * 384 + c]       = hi;
        g_wk[o * 384 + 128 + c] = hi;
        g_wk[o * 384 + 256 + c] = lo;
    }
    for (int i = gtid; i < 128 * 128; i += nthr) {
        int o = i >> 7;
        int c = i & 127;
        float v = Wproj[(size_t)o * CC + c];
        __nv_bfloat16 hi = __float2bfloat16(v);
        __nv_bfloat16 lo = __float2bfloat16(v - __bfloat162float(hi));
        g_wpk[o * 384 + c]       = hi;
        g_wpk[o * 384 + 128 + c] = hi;
        g_wpk[o * 384 + 256 + c] = lo;
    }
}

// ---------------------------------------------------------------------------
// Kernel 1: QKV GEMM via mma.sync bf16 (split-bf16, K-ext 384).
// grid (49, 64), block 256 (8 warps), dyn smem 100352 B, 2 CTAs/SM.
// SMEM: Bsm [64 hw][392 k] bf16 @0 (50176B); A double-buffer 2 x 25088B @50176.
// A chunks (32 o-rows) stream via cp.async, overlapped with MMA compute.
// ---------------------------------------------------------------------------
#define RSE   392          // smem row stride, elems (bf16)
#define RSB   784          // smem row stride, bytes
#define AOFF  50176
#define ABUF  25088
#define SMEM_QKV (50176 + 2 * 25088)

__global__ void __launch_bounds__(256, 2)
qkv_mma_kernel(const float* __restrict__ x, float* __restrict__ out)
{
    extern __shared__ char smem[];
    const uint32_t sb = smem_to_u32(smem);
    __nv_bfloat16* Bsm = reinterpret_cast<__nv_bfloat16*>(smem);

    const int tid  = threadIdx.x;
    const int wid  = tid >> 5;
    const int lane = tid & 31;
    const int hw0  = blockIdx.x * 64;
    const int bt   = blockIdx.y;

    // Prefetch A chunks 0 and 1 (fully hidden behind the B-build phase)
    issue_chunk_copy(sb + AOFF,        g_wk,            tid);
    CP_COMMIT();
    issue_chunk_copy(sb + AOFF + ABUF, g_wk + 32 * 384, tid);
    CP_COMMIT();

    // ---- Build B: X[c][hw0+j] -> Bsm[j][c]=hi, [j][128+c]=lo, [j][256+c]=hi
    {
        const float* xb = x + (size_t)bt * CC * HW;
        for (int i = tid; i < 64 * 128; i += 256) {
            int c = i >> 6;
            int j = i & 63;
            float v = xb[(size_t)c * HW + hw0 + j];
            __nv_bfloat16 hi = __float2bfloat16(v);
            __nv_bfloat16 lo = __float2bfloat16(v - __bfloat162float(hi));
            Bsm[j * RSE + c]       = hi;
            Bsm[j * RSE + 128 + c] = lo;
            Bsm[j * RSE + 256 + c] = hi;
        }
    }

    // Warp tiling: 2 (m) x 4 (n); warp tile 16(o) x 16(hw).
    const int m0l = (wid >> 2) * 16;
    const int n0  = (wid & 3) * 16;

    const int rowA = m0l + (lane & 7) + ((lane >> 3) & 1) * 8;
    const int kA   = (lane >> 4) * 8;
    const uint32_t aOffL = rowA * RSB + kA * 2;       // offset within A buffer
    const int rowB = n0 + (lane & 7) + (lane >> 4) * 8;
    const int kB   = ((lane >> 3) & 1) * 8;
    const uint32_t bBase = sb + rowB * RSB + kB * 2;

    const int gid = lane >> 2;
    const int tg  = lane & 3;

    for (int mt = 0; mt < 12; mt++) {
        CP_WAIT1();                 // chunk mt resident
        __syncthreads();

        const uint32_t aBase = sb + AOFF + (mt & 1) * ABUF + aOffL;
        float d0[4] = {0.f, 0.f, 0.f, 0.f};
        float d1[4] = {0.f, 0.f, 0.f, 0.f};
#pragma unroll
        for (int ks = 0; ks < 24; ks++) {
            uint32_t a0, a1, a2, a3, b0, b1, b2, b3;
            LDSM4(a0, a1, a2, a3, aBase + ks * 32);
            LDSM4(b0, b1, b2, b3, bBase + ks * 32);
            MMA_BF16(d0, a0, a1, a2, a3, b0, b1);
            MMA_BF16(d1, a0, a1, a2, a3, b2, b3);
        }

        // Direct stores: each 4-lane group writes 32B sectors
        {
            int r0g = mt * 32 + m0l + gid;
            size_t base = (size_t)bt * 384 * HW + hw0;
            float2 v;
            v.x = d0[0]; v.y = d0[1];
            *reinterpret_cast<float2*>(out + base + (size_t)r0g * HW + n0 + 2 * tg) = v;
            v.x = d0[2]; v.y = d0[3];
            *reinterpret_cast<float2*>(out + base + (size_t)(r0g + 8) * HW + n0 + 2 * tg) = v;
            v.x = d1[0]; v.y = d1[1];
            *reinterpret_cast<float2*>(out + base + (size_t)r0g * HW + n0 + 8 + 2 * tg) = v;
            v.x = d1[2]; v.y = d1[3];
            *reinterpret_cast<float2*>(out + base + (size_t)(r0g + 8) * HW + n0 + 8 + 2 * tg) = v;
        }
        __syncthreads();            // all reads of buf[mt&1] done

        if (mt + 2 < 12) {
            issue_chunk_copy(sb + AOFF + (mt & 1) * ABUF,
                             g_wk + (size_t)(mt + 2) * 32 * 384, tid);
        }
        CP_COMMIT();                // empty group when nothing issued
    }
}

// ---------------------------------------------------------------------------
// Kernel 2: fused banded attention + projection (mma.sync).
// Per-thread fused score/softmax/Y-build (head cg = tid>>6, column j = tid&63),
// then projection over 4 cp.async-double-buffered 32-row W chunks.
// grid (49, 64), block 256, dyn smem 100352 B, 2 CTAs/SM.
// SMEM: Wbuf 2 x 25088B @0; Ybf [64 hw][392 k] bf16 @50176.
// ---------------------------------------------------------------------------
#define YOFF 50176
#define SMEM_AP (2 * 25088 + 50176)

__global__ void __launch_bounds__(256, 2)
attn_proj_kernel(const float* __restrict__ qkv,
                 const float* __restrict__ bias,
                 float* __restrict__ out)
{
    extern __shared__ char smem[];
    const uint32_t sb = smem_to_u32(smem);
    __nv_bfloat16* Ybf = reinterpret_cast<__nv_bfloat16*>(smem + YOFF);

    const int hw0 = blockIdx.x * 64;
    const int bt  = blockIdx.y;
    const int b   = bt >> 4;
    const int t   = bt & 15;
    const int tid = threadIdx.x;
    const int wid  = tid >> 5;
    const int lane = tid & 31;

    // Prefetch W chunks 0 and 1 (hidden behind the attention phase)
    issue_chunk_copy(sb,         g_wpk,            tid);
    CP_COMMIT();
    issue_chunk_copy(sb + ABUF,  g_wpk + 32 * 384, tid);
    CP_COMMIT();

    bool valid[3];
    size_t kvbase[3];
#pragma unroll
    for (int i = 0; i < 3; i++) {
        int s = t - 2 + i;
        valid[i] = (s >= 0);
        if (s < 0) s = 0;
        kvbase[i] = (size_t)(b * TT + s) * 384 * HW;
    }

    // ---- Fused attention: thread (cg, j) handles head cg at column j
    {
        const int cg = tid >> 6;        // head
        const int j  = tid & 63;
        const int hw = hw0 + j;
        const int c0 = cg * 32;

        const float* qp = qkv + (size_t)bt * 384 * HW + (size_t)c0 * HW + hw;
        const float* k0 = qkv + kvbase[0] + (size_t)(128 + c0) * HW + hw;
        const float* k1 = qkv + kvbase[1] + (size_t)(128 + c0) * HW + hw;
        const float* k2 = qkv + kvbase[2] + (size_t)(128 + c0) * HW + hw;

        float s0 = 0.f, s1 = 0.f, s2 = 0.f;
#pragma unroll 8
        for (int r = 0; r < 32; r++) {
            float qv = qp[(size_t)r * HW];
            s0 = fmaf(qv, k0[(size_t)r * HW], s0);
            s1 = fmaf(qv, k1[(size_t)r * HW], s1);
            s2 = fmaf(qv, k2[(size_t)r * HW], s2);
        }

        s0 *= SCALE; s1 *= SCALE; s2 *= SCALE;
        float m = s2;                         // key i=2 (s=t) always valid
        if (valid[0]) m = fmaxf(m, s0);
        if (valid[1]) m = fmaxf(m, s1);
        float e0 = valid[0] ? expf(s0 - m) : 0.f;
        float e1 = valid[1] ? expf(s1 - m) : 0.f;
        float e2 = expf(s2 - m);
        float inv = 1.f / (e0 + e1 + e2);
        float a0 = e0 * inv, a1 = e1 * inv, a2 = e2 * inv;

        const float* v0 = qkv + kvbase[0] + (size_t)(256 + c0) * HW + hw;
        const float* v1 = qkv + kvbase[1] + (size_t)(256 + c0) * HW + hw;
        const float* v2 = qkv + kvbase[2] + (size_t)(256 + c0) * HW + hw;
#pragma unroll 8
        for (int r = 0; r < 32; r++) {
            float yv = a0 * v0[(size_t)r * HW];
            yv = fmaf(a1, v1[(size_t)r * HW], yv);
            yv = fmaf(a2, v2[(size_t)r * HW], yv);
            __nv_bfloat16 hi = __float2bfloat16(yv);
            __nv_bfloat16 lo = __float2bfloat16(yv - __bfloat162float(hi));
            int cp = c0 + r;
            Ybf[j * RSE + cp]       = hi;
            Ybf[j * RSE + 128 + cp] = lo;
            Ybf[j * RSE + 256 + cp] = hi;
        }
    }

    // ---- Projection: 4 chunks of 32 o-rows, warps 2(m) x 4(n), tile 16x16
    const int m0l = (wid >> 2) * 16;
    const int n0  = (wid & 3) * 16;

    const int rowA = m0l + (lane & 7) + ((lane >> 3) & 1) * 8;
    const int kA   = (lane >> 4) * 8;
    const uint32_t aOffL = rowA * RSB + kA * 2;
    const int rowB = n0 + (lane & 7) + (lane >> 4) * 8;
    const int kB   = ((lane >> 3) & 1) * 8;
    const uint32_t bBase = sb + YOFF + rowB * RSB + kB * 2;

    const int gid = lane >> 2;
    const int tg  = lane & 3;

    for (int ct = 0; ct < 4; ct++) {
        CP_WAIT1();                 // W chunk ct resident
        __syncthreads();            // also publishes Ybf on first iteration

        const uint32_t aBase = sb + (ct & 1) * ABUF + aOffL;
        float d0[4] = {0.f, 0.f, 0.f, 0.f};
        float d1[4] = {0.f, 0.f, 0.f, 0.f};
#pragma unroll
        for (int ks = 0; ks < 24; ks++) {
            uint32_t a0, a1, a2, a3, b0, b1, b2, b3;
            LDSM4(a0, a1, a2, a3, aBase + ks * 32);
            LDSM4(b0, b1, b2, b3, bBase + ks * 32);
            MMA_BF16(d0, a0, a1, a2, a3, b0, b1);
            MMA_BF16(d1, a0, a1, a2, a3, b2, b3);
        }

        // Direct stores with bias
        {
            int og0 = ct * 32 + m0l + gid;
            int og1 = og0 + 8;
            float bv0 = __ldg(bias + og0);
            float bv1 = __ldg(bias + og1);
            size_t base = (size_t)bt * CC * HW + hw0;
            float2 v;
            v.x = d0[0] + bv0; v.y = d0[1] + bv0;
            *reinterpret_cast<float2*>(out + base + (size_t)og0 * HW + n0 + 2 * tg) = v;
            v.x = d0[2] + bv1; v.y = d0[3] + bv1;
            *reinterpret_cast<float2*>(out + base + (size_t)og1 * HW + n0 + 2 * tg) = v;
            v.x = d1[0] + bv0; v.y = d1[1] + bv0;
            *reinterpret_cast<float2*>(out + base + (size_t)og0 * HW + n0 + 8 + 2 * tg) = v;
            v.x = d1[2] + bv1; v.y = d1[3] + bv1;
            *reinterpret_cast<float2*>(out + base + (size_t)og1 * HW + n0 + 8 + 2 * tg) = v;
        }
        __syncthreads();            // all reads of Wbuf[ct&1] done

        if (ct + 2 < 4) {
            issue_chunk_copy(sb + (ct & 1) * ABUF,
                             g_wpk + (size_t)(ct + 2) * 32 * 384, tid);
        }
        CP_COMMIT();
    }
}

// ---------------------------------------------------------------------------
// kernel_launch
// ---------------------------------------------------------------------------
extern "C" void kernel_launch(void* const* d_in, const int* in_sizes, int n_in,
                              void* d_out, int out_size)
{
    const float* x      = (const float*)d_in[0];
    const float* w_qkv  = (const float*)d_in[1];
    const float* w_proj = (const float*)d_in[2];
    const float* b_proj = (const float*)d_in[3];
    float* out = (float*)d_out;

    float* qkv_s = nullptr;
    cudaGetSymbolAddress((void**)&qkv_s, g_qkv);

    cudaFuncSetAttribute(qkv_mma_kernel,
                         cudaFuncAttributeMaxDynamicSharedMemorySize, SMEM_QKV);
    cudaFuncSetAttribute(attn_proj_kernel,
                         cudaFuncAttributeMaxDynamicSharedMemorySize, SMEM_AP);

    // 0) K-extended split-bf16 weights
    prep_w_kernel<<<128, 256>>>(w_qkv, w_proj);
    // 1) QKV GEMM on tensor cores (cp.async pipelined A)
    {
        dim3 grid(HW / 64, BT);
        qkv_mma_kernel<<<grid, 256, SMEM_QKV>>>(x, qkv_s);
    }
    // 2) Fused banded attention + projection (cp.async pipelined W)
    {
        dim3 grid(HW / 64, BT);
        attn_proj_kernel<<<grid, 256, SMEM_AP>>>(qkv_s, b_proj, out);
    }
}

// round 12
// speedup vs baseline: 2.7280x; 1.1120x over previous
#include <cuda_runtime.h>
#include <cuda_bf16.h>
#include <cstdint>
#include <math.h>

#define HW     3136
#define CC     128
#define TT     16
#define BB     4
#define BT     64          // B*T
#define SCALE  0.17677669529663687f   // 1/sqrt(32)

// ---------------------------------------------------------------------------
// Scratch (device globals; no allocations in kernel_launch)
// ---------------------------------------------------------------------------
__device__ float g_qkv[(size_t)BT * 384 * HW];      // [bt][comp 0..383][hw]
// Split-bf16 weights, row-major [o][256]: cols [0,128)=hi, [128,256)=lo.
// K-ext duplication is done via ldmatrix offset tables, not storage.
__device__ __nv_bfloat16 g_wk [384 * 256];          // w_qkv
__device__ __nv_bfloat16 g_wpk[128 * 256];          // w_proj

__device__ __forceinline__ uint32_t smem_to_u32(const void* smem_ptr) {
    uint32_t addr;
    asm("{ .reg .u64 tmp; cvta.to.shared.u64 tmp, %1; cvt.u32.u64 %0, tmp; }"
        : "=r"(addr) : "l"(smem_ptr));
    return addr;
}

// ldmatrix x4: 4 8x8 b16 tiles; lanes [8i,8i+8) give row addresses of tile i.
#define LDSM4(r0, r1, r2, r3, addr) \
    asm volatile("ldmatrix.sync.aligned.m8n8.x4.shared.b16 {%0,%1,%2,%3}, [%4];" \
        : "=r"(r0), "=r"(r1), "=r"(r2), "=r"(r3) : "r"(addr))

// D(16x8,f32) += A(16x16,bf16,row) * B(16x8,bf16,col)
#define MMA_BF16(d, a0, a1, a2, a3, b0, b1) \
    asm volatile("mma.sync.aligned.m16n8k16.row.col.f32.bf16.bf16.f32 " \
        "{%0,%1,%2,%3}, {%4,%5,%6,%7}, {%8,%9}, {%0,%1,%2,%3};" \
        : "+f"((d)[0]), "+f"((d)[1]), "+f"((d)[2]), "+f"((d)[3]) \
        : "r"(a0), "r"(a1), "r"(a2), "r"(a3), "r"(b0), "r"(b1))

#define CP_ASYNC16(saddr, gptr) \
    asm volatile("cp.async.cg.shared.global [%0], [%1], 16;" \
        :: "r"(saddr), "l"(gptr))
#define CP_COMMIT() asm volatile("cp.async.commit_group;" ::: "memory")
#define CP_WAIT1()  asm volatile("cp.async.wait_group 1;" ::: "memory")

// K-step byte offsets implementing the K-ext-384 term structure on
// de-duplicated storage (A blocks [hi,hi,lo], B blocks [hi,lo,hi]):
__device__ __constant__ int AOFFS[24] = {
    0,32,64,96,128,160,192,224,  0,32,64,96,128,160,192,224,
    256,288,320,352,384,416,448,480 };
__device__ __constant__ int BOFFS[24] = {
    0,32,64,96,128,160,192,224,  256,288,320,352,384,416,448,480,
    0,32,64,96,128,160,192,224 };

// Row strides (de-duplicated: 256 bf16 cols + 16B pad)
#define RSE   264          // smem row stride, elems (bf16)
#define RSB   528          // smem row stride, bytes
#define ABUF  16896        // 32 rows x 528 B

// Async copy of one 32-row x 256-col bf16 chunk (src 512B rows) into smem
// (528B row stride). 256 threads, 4 x 16B each.
__device__ __forceinline__ void issue_chunk_copy(uint32_t dstBase,
                                                 const __nv_bfloat16* srcRow0,
                                                 int tid)
{
    const int row = tid >> 3;       // 32 rows
    const int q0  = tid & 7;        // 8 lanes, 16B each, step 128B
    const char* src = reinterpret_cast<const char*>(srcRow0)
                    + (size_t)row * 512 + q0 * 16;
    uint32_t dst = dstBase + row * 528 + q0 * 16;
#pragma unroll
    for (int it = 0; it < 4; it++) {
        CP_ASYNC16(dst + it * 128, src + it * 128);
    }
}

// ---------------------------------------------------------------------------
// Prep: split-bf16 weights (hi|lo) for both gemms. grid 128 x 256.
// ---------------------------------------------------------------------------
__global__ void prep_w_kernel(const float* __restrict__ Wqkv,
                              const float* __restrict__ Wproj)
{
    const int gtid = blockIdx.x * blockDim.x + threadIdx.x;
    const int nthr = gridDim.x * blockDim.x;
    for (int i = gtid; i < 384 * 128; i += nthr) {
        int o = i >> 7;
        int c = i & 127;
        float v = Wqkv[(size_t)o * CC + c];
        __nv_bfloat16 hi = __float2bfloat16(v);
        __nv_bfloat16 lo = __float2bfloat16(v - __bfloat162float(hi));
        g_wk[o * 256 + c]       = hi;
        g_wk[o * 256 + 128 + c] = lo;
    }
    for (int i = gtid; i < 128 * 128; i += nthr) {
        int o = i >> 7;
        int c = i & 127;
        float v = Wproj[(size_t)o * CC + c];
        __nv_bfloat16 hi = __float2bfloat16(v);
        __nv_bfloat16 lo = __float2bfloat16(v - __bfloat162float(hi));
        g_wpk[o * 256 + c]       = hi;
        g_wpk[o * 256 + 128 + c] = lo;
    }
}

// ---------------------------------------------------------------------------
// Kernel 1: QKV GEMM via mma.sync bf16 (split-bf16, K-ext via offset tables).
// grid (49, 64), block 256 (8 warps), dyn smem 67584 B, 3 CTAs/SM.
// SMEM: Bsm [64 hw][264] bf16 @0 (33792B); A double-buffer 2 x 16896B @33792.
// ---------------------------------------------------------------------------
#define AOFF  33792
#define SMEM_QKV (33792 + 2 * 16896)

__global__ void __launch_bounds__(256, 3)
qkv_mma_kernel(const float* __restrict__ x, float* __restrict__ out)
{
    extern __shared__ char smem[];
    const uint32_t sb = smem_to_u32(smem);
    __nv_bfloat16* Bsm = reinterpret_cast<__nv_bfloat16*>(smem);

    const int tid  = threadIdx.x;
    const int wid  = tid >> 5;
    const int lane = tid & 31;
    const int hw0  = blockIdx.x * 64;
    const int bt   = blockIdx.y;

    // Prefetch A chunks 0 and 1 (hidden behind the B-build phase)
    issue_chunk_copy(sb + AOFF,        g_wk,            tid);
    CP_COMMIT();
    issue_chunk_copy(sb + AOFF + ABUF, g_wk + 32 * 256, tid);
    CP_COMMIT();

    // ---- Build B: X[c][hw0+j] -> Bsm[j][c]=hi, [j][128+c]=lo
    {
        const float* xb = x + (size_t)bt * CC * HW;
        for (int i = tid; i < 64 * 128; i += 256) {
            int c = i >> 6;
            int j = i & 63;
            float v = xb[(size_t)c * HW + hw0 + j];
            __nv_bfloat16 hi = __float2bfloat16(v);
            __nv_bfloat16 lo = __float2bfloat16(v - __bfloat162float(hi));
            Bsm[j * RSE + c]       = hi;
            Bsm[j * RSE + 128 + c] = lo;
        }
    }

    // Warp tiling: 2 (m) x 4 (n); warp tile 16(o) x 16(hw).
    const int m0l = (wid >> 2) * 16;
    const int n0  = (wid & 3) * 16;

    const int rowA = m0l + (lane & 7) + ((lane >> 3) & 1) * 8;
    const int kA   = (lane >> 4) * 8;
    const uint32_t aOffL = rowA * RSB + kA * 2;       // offset within A buffer
    const int rowB = n0 + (lane & 7) + (lane >> 4) * 8;
    const int kB   = ((lane >> 3) & 1) * 8;
    const uint32_t bBase = sb + rowB * RSB + kB * 2;

    const int gid = lane >> 2;
    const int tg  = lane & 3;

    for (int mt = 0; mt < 12; mt++) {
        CP_WAIT1();                 // chunk mt resident
        __syncthreads();

        const uint32_t aBase = sb + AOFF + (mt & 1) * ABUF + aOffL;
        float d0[4] = {0.f, 0.f, 0.f, 0.f};
        float d1[4] = {0.f, 0.f, 0.f, 0.f};
#pragma unroll
        for (int ks = 0; ks < 24; ks++) {
            uint32_t a0, a1, a2, a3, b0, b1, b2, b3;
            LDSM4(a0, a1, a2, a3, aBase + AOFFS[ks]);
            LDSM4(b0, b1, b2, b3, bBase + BOFFS[ks]);
            MMA_BF16(d0, a0, a1, a2, a3, b0, b1);
            MMA_BF16(d1, a0, a1, a2, a3, b2, b3);
        }

        // Direct stores: each 4-lane group writes 32B sectors
        {
            int r0g = mt * 32 + m0l + gid;
            size_t base = (size_t)bt * 384 * HW + hw0;
            float2 v;
            v.x = d0[0]; v.y = d0[1];
            *reinterpret_cast<float2*>(out + base + (size_t)r0g * HW + n0 + 2 * tg) = v;
            v.x = d0[2]; v.y = d0[3];
            *reinterpret_cast<float2*>(out + base + (size_t)(r0g + 8) * HW + n0 + 2 * tg) = v;
            v.x = d1[0]; v.y = d1[1];
            *reinterpret_cast<float2*>(out + base + (size_t)r0g * HW + n0 + 8 + 2 * tg) = v;
            v.x = d1[2]; v.y = d1[3];
            *reinterpret_cast<float2*>(out + base + (size_t)(r0g + 8) * HW + n0 + 8 + 2 * tg) = v;
        }
        __syncthreads();            // all reads of buf[mt&1] done

        if (mt + 2 < 12) {
            issue_chunk_copy(sb + AOFF + (mt & 1) * ABUF,
                             g_wk + (size_t)(mt + 2) * 32 * 256, tid);
        }
        CP_COMMIT();                // empty group when nothing issued
    }
}

// ---------------------------------------------------------------------------
// Kernel 2: fused banded attention + projection (mma.sync).
// Per-thread fused score/softmax/Y-build, then projection over 4
// double-buffered 32-row W chunks. grid (49, 64), block 256,
// dyn smem 67584 B, 3 CTAs/SM.
// SMEM: Wbuf 2 x 16896B @0; Ybf [64 hw][264] bf16 @33792.
// ---------------------------------------------------------------------------
#define YOFF 33792
#define SMEM_AP (2 * 16896 + 33792)

__global__ void __launch_bounds__(256, 3)
attn_proj_kernel(const float* __restrict__ qkv,
                 const float* __restrict__ bias,
                 float* __restrict__ out)
{
    extern __shared__ char smem[];
    const uint32_t sb = smem_to_u32(smem);
    __nv_bfloat16* Ybf = reinterpret_cast<__nv_bfloat16*>(smem + YOFF);

    const int hw0 = blockIdx.x * 64;
    const int bt  = blockIdx.y;
    const int b   = bt >> 4;
    const int t   = bt & 15;
    const int tid = threadIdx.x;
    const int wid  = tid >> 5;
    const int lane = tid & 31;

    // Prefetch W chunks 0 and 1 (hidden behind the attention phase)
    issue_chunk_copy(sb,        g_wpk,            tid);
    CP_COMMIT();
    issue_chunk_copy(sb + ABUF, g_wpk + 32 * 256, tid);
    CP_COMMIT();

    bool valid[3];
    size_t kvbase[3];
#pragma unroll
    for (int i = 0; i < 3; i++) {
        int s = t - 2 + i;
        valid[i] = (s >= 0);
        if (s < 0) s = 0;
        kvbase[i] = (size_t)(b * TT + s) * 384 * HW;
    }

    // ---- Fused attention: thread (cg, j) handles head cg at column j
    {
        const int cg = tid >> 6;        // head
        const int j  = tid & 63;
        const int hw = hw0 + j;
        const int c0 = cg * 32;

        const float* qp = qkv + (size_t)bt * 384 * HW + (size_t)c0 * HW + hw;
        const float* k0 = qkv + kvbase[0] + (size_t)(128 + c0) * HW + hw;
        const float* k1 = qkv + kvbase[1] + (size_t)(128 + c0) * HW + hw;
        const float* k2 = qkv + kvbase[2] + (size_t)(128 + c0) * HW + hw;

        float s0 = 0.f, s1 = 0.f, s2 = 0.f;
#pragma unroll 8
        for (int r = 0; r < 32; r++) {
            float qv = qp[(size_t)r * HW];
            s0 = fmaf(qv, k0[(size_t)r * HW], s0);
            s1 = fmaf(qv, k1[(size_t)r * HW], s1);
            s2 = fmaf(qv, k2[(size_t)r * HW], s2);
        }

        s0 *= SCALE; s1 *= SCALE; s2 *= SCALE;
        float m = s2;                         // key i=2 (s=t) always valid
        if (valid[0]) m = fmaxf(m, s0);
        if (valid[1]) m = fmaxf(m, s1);
        float e0 = valid[0] ? expf(s0 - m) : 0.f;
        float e1 = valid[1] ? expf(s1 - m) : 0.f;
        float e2 = expf(s2 - m);
        float inv = 1.f / (e0 + e1 + e2);
        float a0 = e0 * inv, a1 = e1 * inv, a2 = e2 * inv;

        const float* v0 = qkv + kvbase[0] + (size_t)(256 + c0) * HW + hw;
        const float* v1 = qkv + kvbase[1] + (size_t)(256 + c0) * HW + hw;
        const float* v2 = qkv + kvbase[2] + (size_t)(256 + c0) * HW + hw;
#pragma unroll 8
        for (int r = 0; r < 32; r++) {
            float yv = a0 * v0[(size_t)r * HW];
            yv = fmaf(a1, v1[(size_t)r * HW], yv);
            yv = fmaf(a2, v2[(size_t)r * HW], yv);
            __nv_bfloat16 hi = __float2bfloat16(yv);
            __nv_bfloat16 lo = __float2bfloat16(yv - __bfloat162float(hi));
            int cp = c0 + r;
            Ybf[j * RSE + cp]       = hi;
            Ybf[j * RSE + 128 + cp] = lo;
        }
    }

    // ---- Projection: 4 chunks of 32 o-rows, warps 2(m) x 4(n), tile 16x16
    const int m0l = (wid >> 2) * 16;
    const int n0  = (wid & 3) * 16;

    const int rowA = m0l + (lane & 7) + ((lane >> 3) & 1) * 8;
    const int kA   = (lane >> 4) * 8;
    const uint32_t aOffL = rowA * RSB + kA * 2;
    const int rowB = n0 + (lane & 7) + (lane >> 4) * 8;
    const int kB   = ((lane >> 3) & 1) * 8;
    const uint32_t bBase = sb + YOFF + rowB * RSB + kB * 2;

    const int gid = lane >> 2;
    const int tg  = lane & 3;

    for (int ct = 0; ct < 4; ct++) {
        CP_WAIT1();                 // W chunk ct resident
        __syncthreads();            // also publishes Ybf on first iteration

        const uint32_t aBase = sb + (ct & 1) * ABUF + aOffL;
        float d0[4] = {0.f, 0.f, 0.f, 0.f};
        float d1[4] = {0.f, 0.f, 0.f, 0.f};
#pragma unroll
        for (int ks = 0; ks < 24; ks++) {
            uint32_t a0, a1, a2, a3, b0, b1, b2, b3;
            LDSM4(a0, a1, a2, a3, aBase + AOFFS[ks]);
            LDSM4(b0, b1, b2, b3, bBase + BOFFS[ks]);
            MMA_BF16(d0, a0, a1, a2, a3, b0, b1);
            MMA_BF16(d1, a0, a1, a2, a3, b2, b3);
        }

        // Direct stores with bias
        {
            int og0 = ct * 32 + m0l + gid;
            int og1 = og0 + 8;
            float bv0 = __ldg(bias + og0);
            float bv1 = __ldg(bias + og1);
            size_t base = (size_t)bt * CC * HW + hw0;
            float2 v;
            v.x = d0[0] + bv0; v.y = d0[1] + bv0;
            *reinterpret_cast<float2*>(out + base + (size_t)og0 * HW + n0 + 2 * tg) = v;
            v.x = d0[2] + bv1; v.y = d0[3] + bv1;
            *reinterpret_cast<float2*>(out + base + (size_t)og1 * HW + n0 + 2 * tg) = v;
            v.x = d1[0] + bv0; v.y = d1[1] + bv0;
            *reinterpret_cast<float2*>(out + base + (size_t)og0 * HW + n0 + 8 + 2 * tg) = v;
            v.x = d1[2] + bv1; v.y = d1[3] + bv1;
            *reinterpret_cast<float2*>(out + base + (size_t)og1 * HW + n0 + 8 + 2 * tg) = v;
        }
        __syncthreads();            // all reads of Wbuf[ct&1] done

        if (ct + 2 < 4) {
            issue_chunk_copy(sb + (ct & 1) * ABUF,
                             g_wpk + (size_t)(ct + 2) * 32 * 256, tid);
        }
        CP_COMMIT();
    }
}

// ---------------------------------------------------------------------------
// kernel_launch
// ---------------------------------------------------------------------------
extern "C" void kernel_launch(void* const* d_in, const int* in_sizes, int n_in,
                              void* d_out, int out_size)
{
    const float* x      = (const float*)d_in[0];
    const float* w_qkv  = (const float*)d_in[1];
    const float* w_proj = (const float*)d_in[2];
    const float* b_proj = (const float*)d_in[3];
    float* out = (float*)d_out;

    float* qkv_s = nullptr;
    cudaGetSymbolAddress((void**)&qkv_s, g_qkv);

    cudaFuncSetAttribute(qkv_mma_kernel,
                         cudaFuncAttributeMaxDynamicSharedMemorySize, SMEM_QKV);
    cudaFuncSetAttribute(attn_proj_kernel,
                         cudaFuncAttributeMaxDynamicSharedMemorySize, SMEM_AP);

    // 0) Split-bf16 weights (hi|lo, de-duplicated)
    prep_w_kernel<<<128, 256>>>(w_qkv, w_proj);
    // 1) QKV GEMM on tensor cores (cp.async pipelined A)
    {
        dim3 grid(HW / 64, BT);
        qkv_mma_kernel<<<grid, 256, SMEM_QKV>>>(x, qkv_s);
    }
    // 2) Fused banded attention + projection (cp.async pipelined W)
    {
        dim3 grid(HW / 64, BT);
        attn_proj_kernel<<<grid, 256, SMEM_AP>>>(qkv_s, b_proj, out);
    }
}

// round 15
// speedup vs baseline: 3.0495x; 1.1178x over previous
#include <cuda_runtime.h>
#include <cuda_bf16.h>
#include <cstdint>
#include <math.h>

#define HW     3136
#define CC     128
#define TT     16
#define BB     4
#define BT     64          // B*T
#define SCALE  0.17677669529663687f   // 1/sqrt(32)

// ---------------------------------------------------------------------------
// Scratch (device globals; no allocations in kernel_launch)
// ---------------------------------------------------------------------------
__device__ float g_qkv[(size_t)BT * 384 * HW];      // [bt][comp 0..383][hw]
// Split-bf16 weights, row-major [o][256]: cols [0,128)=hi, [128,256)=lo.
// K-ext duplication is done via ldmatrix offset tables, not storage.
__device__ __nv_bfloat16 g_wk [384 * 256];          // w_qkv
__device__ __nv_bfloat16 g_wpk[128 * 256];          // w_proj

__device__ __forceinline__ uint32_t smem_to_u32(const void* smem_ptr) {
    uint32_t addr;
    asm("{ .reg .u64 tmp; cvta.to.shared.u64 tmp, %1; cvt.u32.u64 %0, tmp; }"
        : "=r"(addr) : "l"(smem_ptr));
    return addr;
}

// ldmatrix x4: 4 8x8 b16 tiles; lanes [8i,8i+8) give row addresses of tile i.
#define LDSM4(r0, r1, r2, r3, addr) \
    asm volatile("ldmatrix.sync.aligned.m8n8.x4.shared.b16 {%0,%1,%2,%3}, [%4];" \
        : "=r"(r0), "=r"(r1), "=r"(r2), "=r"(r3) : "r"(addr))

// D(16x8,f32) += A(16x16,bf16,row) * B(16x8,bf16,col)
#define MMA_BF16(d, a0, a1, a2, a3, b0, b1) \
    asm volatile("mma.sync.aligned.m16n8k16.row.col.f32.bf16.bf16.f32 " \
        "{%0,%1,%2,%3}, {%4,%5,%6,%7}, {%8,%9}, {%0,%1,%2,%3};" \
        : "+f"((d)[0]), "+f"((d)[1]), "+f"((d)[2]), "+f"((d)[3]) \
        : "r"(a0), "r"(a1), "r"(a2), "r"(a3), "r"(b0), "r"(b1))

#define CP_ASYNC16(saddr, gptr) \
    asm volatile("cp.async.cg.shared.global [%0], [%1], 16;" \
        :: "r"(saddr), "l"(gptr))
#define CP_COMMIT() asm volatile("cp.async.commit_group;" ::: "memory")
#define CP_WAIT1()  asm volatile("cp.async.wait_group 1;" ::: "memory")

// K-step byte offsets implementing the K-ext-384 term structure on
// de-duplicated storage (A blocks [hi,hi,lo], B blocks [hi,lo,hi]):
__device__ __constant__ int AOFFS[24] = {
    0,32,64,96,128,160,192,224,  0,32,64,96,128,160,192,224,
    256,288,320,352,384,416,448,480 };
__device__ __constant__ int BOFFS[24] = {
    0,32,64,96,128,160,192,224,  256,288,320,352,384,416,448,480,
    0,32,64,96,128,160,192,224 };

// Row strides (de-duplicated: 256 bf16 cols + 16B pad)
#define RSE   264          // smem row stride, elems (bf16)
#define RSB   528          // smem row stride, bytes
#define ABUF  16896        // 32 rows x 528 B
#define BTILE 33792        // 64 rows x 528 B

// Async copy of one 32-row x 256-col bf16 chunk (src 512B rows) into smem
// (528B row stride). 256 threads, 4 x 16B each.
__device__ __forceinline__ void issue_chunk_copy(uint32_t dstBase,
                                                 const __nv_bfloat16* srcRow0,
                                                 int tid)
{
    const int row = tid >> 3;       // 32 rows
    const int q0  = tid & 7;        // 8 lanes, 16B each, step 128B
    const char* src = reinterpret_cast<const char*>(srcRow0)
                    + (size_t)row * 512 + q0 * 16;
    uint32_t dst = dstBase + row * 528 + q0 * 16;
#pragma unroll
    for (int it = 0; it < 4; it++) {
        CP_ASYNC16(dst + it * 128, src + it * 128);
    }
}

// ---------------------------------------------------------------------------
// Prep: split-bf16 weights (hi|lo) for both gemms. grid 128 x 256.
// ---------------------------------------------------------------------------
__global__ void prep_w_kernel(const float* __restrict__ Wqkv,
                              const float* __restrict__ Wproj)
{
    const int gtid = blockIdx.x * blockDim.x + threadIdx.x;
    const int nthr = gridDim.x * blockDim.x;
    for (int i = gtid; i < 384 * 128; i += nthr) {
        int o = i >> 7;
        int c = i & 127;
        float v = Wqkv[(size_t)o * CC + c];
        __nv_bfloat16 hi = __float2bfloat16(v);
        __nv_bfloat16 lo = __float2bfloat16(v - __bfloat162float(hi));
        g_wk[o * 256 + c]       = hi;
        g_wk[o * 256 + 128 + c] = lo;
    }
    for (int i = gtid; i < 128 * 128; i += nthr) {
        int o = i >> 7;
        int c = i & 127;
        float v = Wproj[(size_t)o * CC + c];
        __nv_bfloat16 hi = __float2bfloat16(v);
        __nv_bfloat16 lo = __float2bfloat16(v - __bfloat162float(hi));
        g_wpk[o * 256 + c]       = hi;
        g_wpk[o * 256 + 128 + c] = lo;
    }
}

// ---------------------------------------------------------------------------
// Kernel 1: QKV GEMM, 2 bt per CTA (B tiles for both resident; W chunks
// amortized over 2x MMA work; per-warp 3 LDSM4 : 4 MMA in the hot loop).
// grid (49, 32), block 256 (8 warps), dyn smem 101376 B, 2 CTAs/SM.
// SMEM: Bsm0 @0, Bsm1 @33792 (each 64x528); A double-buffer 2x16896 @67584.
// ---------------------------------------------------------------------------
#define AQOFF 67584
#define SMEM_QKV (2 * BTILE + 2 * ABUF)

__global__ void __launch_bounds__(256, 2)
qkv_mma_kernel(const float* __restrict__ x, float* __restrict__ out)
{
    extern __shared__ char smem[];
    const uint32_t sb = smem_to_u32(smem);

    const int tid  = threadIdx.x;
    const int wid  = tid >> 5;
    const int lane = tid & 31;
    const int hw0  = blockIdx.x * 64;
    const int bt0  = blockIdx.y * 2;

    // Prefetch A chunks 0 and 1 (hidden behind the B-build phase)
    issue_chunk_copy(sb + AQOFF,        g_wk,            tid);
    CP_COMMIT();
    issue_chunk_copy(sb + AQOFF + ABUF, g_wk + 32 * 256, tid);
    CP_COMMIT();

    // ---- Build B tiles for bt0 and bt1
#pragma unroll
    for (int p = 0; p < 2; p++) {
        __nv_bfloat16* Bp = reinterpret_cast<__nv_bfloat16*>(smem + p * BTILE);
        const float* xb = x + (size_t)(bt0 + p) * CC * HW;
        for (int i = tid; i < 64 * 128; i += 256) {
            int c = i >> 6;
            int j = i & 63;
            float v = xb[(size_t)c * HW + hw0 + j];
            __nv_bfloat16 hi = __float2bfloat16(v);
            __nv_bfloat16 lo = __float2bfloat16(v - __bfloat162float(hi));
            Bp[j * RSE + c]       = hi;
            Bp[j * RSE + 128 + c] = lo;
        }
    }

    // Warp tiling: 2 (m) x 4 (n); warp tile 16(o) x 16(hw) per bt.
    const int m0l = (wid >> 2) * 16;
    const int n0  = (wid & 3) * 16;

    const int rowA = m0l + (lane & 7) + ((lane >> 3) & 1) * 8;
    const int kA   = (lane >> 4) * 8;
    const uint32_t aOffL = rowA * RSB + kA * 2;       // offset within A buffer
    const int rowB = n0 + (lane & 7) + (lane >> 4) * 8;
    const int kB   = ((lane >> 3) & 1) * 8;
    const uint32_t b0Base = sb + rowB * RSB + kB * 2;
    const uint32_t b1Base = b0Base + BTILE;

    const int gid = lane >> 2;
    const int tg  = lane & 3;

    for (int mt = 0; mt < 12; mt++) {
        CP_WAIT1();                 // chunk mt resident
        __syncthreads();

        const uint32_t aBase = sb + AQOFF + (mt & 1) * ABUF + aOffL;
        float d00[4] = {0.f, 0.f, 0.f, 0.f};
        float d01[4] = {0.f, 0.f, 0.f, 0.f};
        float d10[4] = {0.f, 0.f, 0.f, 0.f};
        float d11[4] = {0.f, 0.f, 0.f, 0.f};
#pragma unroll
        for (int ks = 0; ks < 24; ks++) {
            uint32_t a0, a1, a2, a3;
            uint32_t p0, p1, p2, p3;
            uint32_t q0r, q1r, q2r, q3r;
            LDSM4(a0, a1, a2, a3, aBase + AOFFS[ks]);
            LDSM4(p0, p1, p2, p3, b0Base + BOFFS[ks]);
            LDSM4(q0r, q1r, q2r, q3r, b1Base + BOFFS[ks]);
            MMA_BF16(d00, a0, a1, a2, a3, p0, p1);
            MMA_BF16(d01, a0, a1, a2, a3, p2, p3);
            MMA_BF16(d10, a0, a1, a2, a3, q0r, q1r);
            MMA_BF16(d11, a0, a1, a2, a3, q2r, q3r);
        }

        // Direct stores: each 4-lane group writes 32B sectors
        {
            int r0g = mt * 32 + m0l + gid;
            size_t base0 = (size_t)bt0 * 384 * HW + hw0;
            size_t base1 = base0 + (size_t)384 * HW;
            float2 v;
            v.x = d00[0]; v.y = d00[1];
            *reinterpret_cast<float2*>(out + base0 + (size_t)r0g * HW + n0 + 2 * tg) = v;
            v.x = d00[2]; v.y = d00[3];
            *reinterpret_cast<float2*>(out + base0 + (size_t)(r0g + 8) * HW + n0 + 2 * tg) = v;
            v.x = d01[0]; v.y = d01[1];
            *reinterpret_cast<float2*>(out + base0 + (size_t)r0g * HW + n0 + 8 + 2 * tg) = v;
            v.x = d01[2]; v.y = d01[3];
            *reinterpret_cast<float2*>(out + base0 + (size_t)(r0g + 8) * HW + n0 + 8 + 2 * tg) = v;
            v.x = d10[0]; v.y = d10[1];
            *reinterpret_cast<float2*>(out + base1 + (size_t)r0g * HW + n0 + 2 * tg) = v;
            v.x = d10[2]; v.y = d10[3];
            *reinterpret_cast<float2*>(out + base1 + (size_t)(r0g + 8) * HW + n0 + 2 * tg) = v;
            v.x = d11[0]; v.y = d11[1];
            *reinterpret_cast<float2*>(out + base1 + (size_t)r0g * HW + n0 + 8 + 2 * tg) = v;
            v.x = d11[2]; v.y = d11[3];
            *reinterpret_cast<float2*>(out + base1 + (size_t)(r0g + 8) * HW + n0 + 8 + 2 * tg) = v;
        }
        __syncthreads();            // all reads of buf[mt&1] done

        if (mt + 2 < 12) {
            issue_chunk_copy(sb + AQOFF + (mt & 1) * ABUF,
                             g_wk + (size_t)(mt + 2) * 32 * 256, tid);
        }
        CP_COMMIT();                // empty group when nothing issued
    }
}

// ---------------------------------------------------------------------------
// Kernel 2: fused banded attention + projection, 2 bt per CTA.
// grid (49, 32), block 256, dyn smem 101376 B, 2 CTAs/SM.
// SMEM: Wbuf 2x16896 @0; Ybf0 @33792, Ybf1 @67584 (each 64x528 bf16).
// ---------------------------------------------------------------------------
#define YOFF0 33792
#define YOFF1 67584
#define SMEM_AP (2 * ABUF + 2 * BTILE)

__global__ void __launch_bounds__(256, 2)
attn_proj_kernel(const float* __restrict__ qkv,
                 const float* __restrict__ bias,
                 float* __restrict__ out)
{
    extern __shared__ char smem[];
    const uint32_t sb = smem_to_u32(smem);

    const int hw0 = blockIdx.x * 64;
    const int bt0 = blockIdx.y * 2;
    const int tid = threadIdx.x;
    const int wid  = tid >> 5;
    const int lane = tid & 31;

    // Prefetch W chunks 0 and 1 (hidden behind the attention phase)
    issue_chunk_copy(sb,        g_wpk,            tid);
    CP_COMMIT();
    issue_chunk_copy(sb + ABUF, g_wpk + 32 * 256, tid);
    CP_COMMIT();

    // ---- Fused attention for bt0 and bt1: thread (cg, j) per head/column
#pragma unroll
    for (int p = 0; p < 2; p++) {
        const int bt = bt0 + p;
        const int b  = bt >> 4;
        const int t  = bt & 15;
        __nv_bfloat16* Ybf = reinterpret_cast<__nv_bfloat16*>(
            smem + (p ? YOFF1 : YOFF0));

        bool valid[3];
        size_t kvbase[3];
#pragma unroll
        for (int i = 0; i < 3; i++) {
            int s = t - 2 + i;
            valid[i] = (s >= 0);
            if (s < 0) s = 0;
            kvbase[i] = (size_t)(b * TT + s) * 384 * HW;
        }

        const int cg = tid >> 6;        // head
        const int j  = tid & 63;
        const int hw = hw0 + j;
        const int c0 = cg * 32;

        const float* qp = qkv + (size_t)bt * 384 * HW + (size_t)c0 * HW + hw;
        const float* k0 = qkv + kvbase[0] + (size_t)(128 + c0) * HW + hw;
        const float* k1 = qkv + kvbase[1] + (size_t)(128 + c0) * HW + hw;
        const float* k2 = qkv + kvbase[2] + (size_t)(128 + c0) * HW + hw;

        float s0 = 0.f, s1 = 0.f, s2 = 0.f;
#pragma unroll 8
        for (int r = 0; r < 32; r++) {
            float qv = qp[(size_t)r * HW];
            s0 = fmaf(qv, k0[(size_t)r * HW], s0);
            s1 = fmaf(qv, k1[(size_t)r * HW], s1);
            s2 = fmaf(qv, k2[(size_t)r * HW], s2);
        }

        s0 *= SCALE; s1 *= SCALE; s2 *= SCALE;
        float m = s2;                         // key i=2 (s=t) always valid
        if (valid[0]) m = fmaxf(m, s0);
        if (valid[1]) m = fmaxf(m, s1);
        float e0 = valid[0] ? expf(s0 - m) : 0.f;
        float e1 = valid[1] ? expf(s1 - m) : 0.f;
        float e2 = expf(s2 - m);
        float inv = 1.f / (e0 + e1 + e2);
        float a0 = e0 * inv, a1 = e1 * inv, a2 = e2 * inv;

        const float* v0 = qkv + kvbase[0] + (size_t)(256 + c0) * HW + hw;
        const float* v1 = qkv + kvbase[1] + (size_t)(256 + c0) * HW + hw;
        const float* v2 = qkv + kvbase[2] + (size_t)(256 + c0) * HW + hw;
#pragma unroll 8
        for (int r = 0; r < 32; r++) {
            float yv = a0 * v0[(size_t)r * HW];
            yv = fmaf(a1, v1[(size_t)r * HW], yv);
            yv = fmaf(a2, v2[(size_t)r * HW], yv);
            __nv_bfloat16 hi = __float2bfloat16(yv);
            __nv_bfloat16 lo = __float2bfloat16(yv - __bfloat162float(hi));
            int cp = c0 + r;
            Ybf[j * RSE + cp]       = hi;
            Ybf[j * RSE + 128 + cp] = lo;
        }
    }

    // ---- Projection: 4 chunks of 32 o-rows; warps 2(m) x 4(n), per-bt 16x16
    const int m0l = (wid >> 2) * 16;
    const int n0  = (wid & 3) * 16;

    const int rowA = m0l + (lane & 7) + ((lane >> 3) & 1) * 8;
    const int kA   = (lane >> 4) * 8;
    const uint32_t aOffL = rowA * RSB + kA * 2;
    const int rowB = n0 + (lane & 7) + (lane >> 4) * 8;
    const int kB   = ((lane >> 3) & 1) * 8;
    const uint32_t b0Base = sb + YOFF0 + rowB * RSB + kB * 2;
    const uint32_t b1Base = sb + YOFF1 + rowB * RSB + kB * 2;

    const int gid = lane >> 2;
    const int tg  = lane & 3;

    for (int ct = 0; ct < 4; ct++) {
        CP_WAIT1();                 // W chunk ct resident
        __syncthreads();            // also publishes Ybf on first iteration

        const uint32_t aBase = sb + (ct & 1) * ABUF + aOffL;
        float d00[4] = {0.f, 0.f, 0.f, 0.f};
        float d01[4] = {0.f, 0.f, 0.f, 0.f};
        float d10[4] = {0.f, 0.f, 0.f, 0.f};
        float d11[4] = {0.f, 0.f, 0.f, 0.f};
#pragma unroll
        for (int ks = 0; ks < 24; ks++) {
            uint32_t a0, a1, a2, a3;
            uint32_t p0, p1, p2, p3;
            uint32_t q0r, q1r, q2r, q3r;
            LDSM4(a0, a1, a2, a3, aBase + AOFFS[ks]);
            LDSM4(p0, p1, p2, p3, b0Base + BOFFS[ks]);
            LDSM4(q0r, q1r, q2r, q3r, b1Base + BOFFS[ks]);
            MMA_BF16(d00, a0, a1, a2, a3, p0, p1);
            MMA_BF16(d01, a0, a1, a2, a3, p2, p3);
            MMA_BF16(d10, a0, a1, a2, a3, q0r, q1r);
            MMA_BF16(d11, a0, a1, a2, a3, q2r, q3r);
        }

        // Direct stores with bias
        {
            int og0 = ct * 32 + m0l + gid;
            int og1 = og0 + 8;
            float bv0 = __ldg(bias + og0);
            float bv1 = __ldg(bias + og1);
            size_t base0 = (size_t)bt0 * CC * HW + hw0;
            size_t base1 = base0 + (size_t)CC * HW;
            float2 v;
            v.x = d00[0] + bv0; v.y = d00[1] + bv0;
            *reinterpret_cast<float2*>(out + base0 + (size_t)og0 * HW + n0 + 2 * tg) = v;
            v.x = d00[2] + bv1; v.y = d00[3] + bv1;
            *reinterpret_cast<float2*>(out + base0 + (size_t)og1 * HW + n0 + 2 * tg) = v;
            v.x = d01[0] + bv0; v.y = d01[1] + bv0;
            *reinterpret_cast<float2*>(out + base0 + (size_t)og0 * HW + n0 + 8 + 2 * tg) = v;
            v.x = d01[2] + bv1; v.y = d01[3] + bv1;
            *reinterpret_cast<float2*>(out + base0 + (size_t)og1 * HW + n0 + 8 + 2 * tg) = v;
            v.x = d10[0] + bv0; v.y = d10[1] + bv0;
            *reinterpret_cast<float2*>(out + base1 + (size_t)og0 * HW + n0 + 2 * tg) = v;
            v.x = d10[2] + bv1; v.y = d10[3] + bv1;
            *reinterpret_cast<float2*>(out + base1 + (size_t)og1 * HW + n0 + 2 * tg) = v;
            v.x = d11[0] + bv0; v.y = d11[1] + bv0;
            *reinterpret_cast<float2*>(out + base1 + (size_t)og0 * HW + n0 + 8 + 2 * tg) = v;
            v.x = d11[2] + bv1; v.y = d11[3] + bv1;
            *reinterpret_cast<float2*>(out + base1 + (size_t)og1 * HW + n0 + 8 + 2 * tg) = v;
        }
        __syncthreads();            // all reads of Wbuf[ct&1] done

        if (ct + 2 < 4) {
            issue_chunk_copy(sb + (ct & 1) * ABUF,
                             g_wpk + (size_t)(ct + 2) * 32 * 256, tid);
        }
        CP_COMMIT();
    }
}

// ---------------------------------------------------------------------------
// kernel_launch
// ---------------------------------------------------------------------------
extern "C" void kernel_launch(void* const* d_in, const int* in_sizes, int n_in,
                              void* d_out, int out_size)
{
    const float* x      = (const float*)d_in[0];
    const float* w_qkv  = (const float*)d_in[1];
    const float* w_proj = (const float*)d_in[2];
    const float* b_proj = (const float*)d_in[3];
    float* out = (float*)d_out;

    float* qkv_s = nullptr;
    cudaGetSymbolAddress((void**)&qkv_s, g_qkv);

    cudaFuncSetAttribute(qkv_mma_kernel,
                         cudaFuncAttributeMaxDynamicSharedMemorySize, SMEM_QKV);
    cudaFuncSetAttribute(attn_proj_kernel,
                         cudaFuncAttributeMaxDynamicSharedMemorySize, SMEM_AP);

    // 0) Split-bf16 weights (hi|lo, de-duplicated)
    prep_w_kernel<<<128, 256>>>(w_qkv, w_proj);
    // 1) QKV GEMM on tensor cores (2 bt per CTA, cp.async pipelined A)
    {
        dim3 grid(HW / 64, BT / 2);
        qkv_mma_kernel<<<grid, 256, SMEM_QKV>>>(x, qkv_s);
    }
    // 2) Fused banded attention + projection (2 bt per CTA)
    {
        dim3 grid(HW / 64, BT / 2);
        attn_proj_kernel<<<grid, 256, SMEM_AP>>>(qkv_s, b_proj, out);
    }
}